// round 9
// baseline (speedup 1.0000x reference)
#include <cuda_runtime.h>
#include <cstdint>
#include <cstring>

#define NNODES 32768
#define NEDGES 262144
#define CC 128
#define NOUTR 8192
#define NVROWS 24576
#define NAROWS 8192

// list ids: 0=ecA(-2) 1=b1[0,1] 2=b2[-1,0] 3=b3[-1,1] 4=vpa(-3) 5=acv(3)
#define NLISTS 6

// ------------------------- scratch (static device, no allocs) -------------------------
__device__ float g_X  [NNODES*CC];
__device__ float g_XAG[NNODES*CC];
__device__ float g_XV2[NNODES*CC];
__device__ float g_UVA[NNODES*256];
__device__ float g_UVB[NNODES*768];
__device__ float g_H  [3][NNODES*CC];
__device__ float g_CAT[3][NOUTR*256];
__device__ float g_SOUT[3][NOUTR*CC];
__device__ float g_ARES[NNODES];
__device__ int   g_bcnt[NLISTS][NNODES];
__device__ int   g_browoff[NLISTS][NNODES+1];
__device__ int   g_bcur[NLISTS][NNODES];
__device__ int   g_bsrc[NLISTS][NEDGES];
__device__ float g_WUVA[CC*256];
__device__ float g_BUVA[256];
__device__ float g_WUVB[CC*768];
__device__ float g_BUVB[768];
__device__ float g_WCAT[256*CC];

// ------------------------- small helpers -------------------------
__device__ __forceinline__ float4 f4max(float4 a, float4 b){
    return make_float4(fmaxf(a.x,b.x),fmaxf(a.y,b.y),fmaxf(a.z,b.z),fmaxf(a.w,b.w));
}
__device__ __forceinline__ float4 f4relu(float4 a){
    return make_float4(fmaxf(a.x,0.f),fmaxf(a.y,0.f),fmaxf(a.z,0.f),fmaxf(a.w,0.f));
}
__device__ __forceinline__ void fma2(unsigned long long& acc, unsigned long long w, unsigned long long t){
    asm("fma.rn.f32x2 %0, %1, %2, %0;" : "+l"(acc) : "l"(w), "l"(t));
}

// ------------------------- CSR build: 6 masked lists -------------------------
__global__ void zero_cnt_kernel(){
    int i = blockIdx.x*blockDim.x + threadIdx.x;
    if (i < NNODES){
        #pragma unroll
        for (int b = 0; b < NLISTS; b++) g_bcnt[b][i] = 0;
    }
}

__global__ void hist_kernel(const int* __restrict__ ei, const int* __restrict__ ea){
    int e = blockIdx.x*blockDim.x + threadIdx.x;
    if (e < NEDGES){
        int d = ei[NEDGES + e];
        int a = ea[e];
        if (a == -2)            atomicAdd(&g_bcnt[0][d], 1);
        if (a >= 0  && a <= 1)  atomicAdd(&g_bcnt[1][d], 1);
        if (a >= -1 && a <= 0)  atomicAdd(&g_bcnt[2][d], 1);
        if (a >= -1 && a <= 1)  atomicAdd(&g_bcnt[3][d], 1);
        if (a == -3)            atomicAdd(&g_bcnt[4][d], 1);
        if (a == 3)             atomicAdd(&g_bcnt[5][d], 1);
    }
}

__global__ void scan_kernel(){
    __shared__ int sh[1024];
    int tid = threadIdx.x;
    for (int b = 0; b < NLISTS; b++){
        int* cnt = g_bcnt[b];
        int* ro  = g_browoff[b];
        int* cur = g_bcur[b];
        int base = tid * 32;
        int s = 0;
        #pragma unroll
        for (int j = 0; j < 32; j++) s += cnt[base + j];
        sh[tid] = s;
        __syncthreads();
        int own = s;
        for (int off = 1; off < 1024; off <<= 1){
            int v = (tid >= off) ? sh[tid - off] : 0;
            __syncthreads();
            sh[tid] += v;
            __syncthreads();
        }
        int run = sh[tid] - own;
        for (int j = 0; j < 32; j++){
            ro[base + j] = run;
            cur[base + j] = run;
            run += cnt[base + j];
        }
        if (tid == 1023) ro[NNODES] = run;
        __syncthreads();
    }
}

__global__ void scatter_kernel(const int* __restrict__ ei, const int* __restrict__ ea){
    int e = blockIdx.x*blockDim.x + threadIdx.x;
    if (e < NEDGES){
        int d = ei[NEDGES + e];
        int s = ei[e];
        int a = ea[e];
        if (a == -2)           { int q = atomicAdd(&g_bcur[0][d], 1); g_bsrc[0][q] = s; }
        if (a >= 0  && a <= 1) { int q = atomicAdd(&g_bcur[1][d], 1); g_bsrc[1][q] = s; }
        if (a >= -1 && a <= 0) { int q = atomicAdd(&g_bcur[2][d], 1); g_bsrc[2][q] = s; }
        if (a >= -1 && a <= 1) { int q = atomicAdd(&g_bcur[3][d], 1); g_bsrc[3][q] = s; }
        if (a == -3)           { int q = atomicAdd(&g_bcur[4][d], 1); g_bsrc[4][q] = s; }
        if (a == 3)            { int q = atomicAdd(&g_bcur[5][d], 1); g_bsrc[5][q] = s; }
    }
}

// ------------------------- weight prep -------------------------
__global__ void prep_kernel(const float* __restrict__ ecA_W1, const float* __restrict__ ecA_b1,
                            const float* __restrict__ ec1_W1, const float* __restrict__ ec1_b1,
                            const float* __restrict__ ec2_W1, const float* __restrict__ ec2_b1,
                            const float* __restrict__ ec3_W1, const float* __restrict__ ec3_b1,
                            const float* __restrict__ Wl, const float* __restrict__ Wr){
    int id = blockIdx.x*blockDim.x + threadIdx.x;
    if (id < CC*256){
        int k = id >> 8, c = id & 255;
        float v;
        if (c < 128) v = ecA_W1[k*128 + c] - ecA_W1[(128+k)*128 + c];
        else         v = ecA_W1[(128+k)*128 + (c-128)];
        g_WUVA[k*256 + c] = v;
    }
    if (id < CC*768){
        int k = id / 768, c = id % 768;
        int b = c >> 8, cc = c & 255;
        const float* W1 = (b==0)? ec1_W1 : (b==1)? ec2_W1 : ec3_W1;
        float v;
        if (cc < 128) v = W1[k*128 + cc] - W1[(128+k)*128 + cc];
        else          v = W1[(128+k)*128 + (cc-128)];
        g_WUVB[k*768 + c] = v;
    }
    if (id < 256*CC){
        int k = id >> 7, c = id & 127;
        g_WCAT[id] = (k < 128) ? Wl[k*128 + c] : Wr[(k-128)*128 + c];
    }
    if (id < 256) g_BUVA[id] = (id < 128) ? ecA_b1[id] : 0.f;
    if (id < 768){
        int b = id >> 8, cc = id & 255;
        const float* bb = (b==0)? ec1_b1 : (b==1)? ec2_b1 : ec3_b1;
        g_BUVB[id] = (cc < 128) ? bb[cc] : 0.f;
    }
}

// ------------------------- TF32 tensor-core GEMM (3-pass error-compensated) -------------------------
__device__ __forceinline__ void split_tf32(float x, uint32_t& h, uint32_t& l){
    uint32_t hh; asm("cvt.rna.tf32.f32 %0, %1;" : "=r"(hh) : "f"(x));
    float lf = x - __uint_as_float(hh);
    uint32_t ll; asm("cvt.rna.tf32.f32 %0, %1;" : "=r"(ll) : "f"(lf));
    h = hh; l = ll;
}

__device__ __forceinline__ void mma8(float* c, const uint32_t* a, uint32_t b0, uint32_t b1){
    asm volatile("mma.sync.aligned.m16n8k8.row.col.f32.tf32.tf32.f32 "
        "{%0,%1,%2,%3},{%4,%5,%6,%7},{%8,%9},{%0,%1,%2,%3};"
        : "+f"(c[0]),"+f"(c[1]),"+f"(c[2]),"+f"(c[3])
        : "r"(a[0]),"r"(a[1]),"r"(a[2]),"r"(a[3]),"r"(b0),"r"(b1));
}

// Block tile 128x128, BK=16. 8 warps (2m x 4n), warp tile 64x32.
template<bool RELU, bool ACC>
__device__ __forceinline__ void tgemm_body(const float* __restrict__ A,
                                           const float* __restrict__ B,
                                           const float* __restrict__ bias,
                                           float* __restrict__ C,
                                           int N, int K,
                                           int m0, int n0,
                                           uint32_t* As, uint32_t* Bs){
    int tid = threadIdx.x;
    int wid = tid>>5, lane = tid&31;
    int g = lane>>2, t = lane&3;
    int mtb = (wid>>2)*4;
    int ntb = (wid&3)*4;
    float acc[4][4][4];
    #pragma unroll
    for(int i=0;i<4;i++)
        #pragma unroll
        for(int j=0;j<4;j++)
            #pragma unroll
            for(int r=0;r<4;r++) acc[i][j][r]=0.f;

    for (int k0=0; k0<K; k0+=16){
        #pragma unroll
        for (int s0=0; s0<2; s0++){
            int s = tid + s0*256;
            int mt = s>>6, kt=(s>>5)&1, ln=s&31;
            int gg=ln>>2, tt=ln&3;
            const float* p  = A + (size_t)(m0+mt*16+gg)*K + (k0+kt*8+tt);
            const float* p8 = p + (size_t)8*K;
            float a0=p[0], a2=p[4], a1=p8[0], a3=p8[4];
            uint32_t h0,l0,h1,l1,h2,l2,h3,l3;
            split_tf32(a0,h0,l0); split_tf32(a1,h1,l1);
            split_tf32(a2,h2,l2); split_tf32(a3,h3,l3);
            uint32_t* d = As + (mt*2+kt)*256 + ln;
            d[0]=h0; d[32]=h1; d[64]=h2; d[96]=h3;
            d[128]=l0; d[160]=l1; d[192]=l2; d[224]=l3;
        }
        #pragma unroll
        for (int s0=0; s0<4; s0++){
            int s = tid + s0*256;
            int nt = s>>6, kt=(s>>5)&1, ln=s&31;
            int gg=ln>>2, tt=ln&3;
            const float* p = B + (size_t)(k0+kt*8+tt)*N + (n0+nt*8+gg);
            float b0=p[0], b1=p[(size_t)4*N];
            uint32_t h0,l0,h1,l1;
            split_tf32(b0,h0,l0); split_tf32(b1,h1,l1);
            uint32_t* d = Bs + (nt*2+kt)*128 + ln;
            d[0]=h0; d[32]=h1; d[64]=l0; d[96]=l1;
        }
        __syncthreads();
        #pragma unroll
        for (int kt=0; kt<2; kt++){
            uint32_t ah[4][4], al[4][4];
            #pragma unroll
            for (int i=0;i<4;i++){
                const uint32_t* p = As + ((mtb+i)*2+kt)*256 + lane;
                #pragma unroll
                for (int r=0;r<4;r++){ ah[i][r]=p[r*32]; al[i][r]=p[128+r*32]; }
            }
            #pragma unroll
            for (int j=0;j<4;j++){
                const uint32_t* p = Bs + ((ntb+j)*2+kt)*128 + lane;
                uint32_t b0h=p[0], b1h=p[32], b0l=p[64], b1l=p[96];
                #pragma unroll
                for (int i=0;i<4;i++){
                    mma8(acc[i][j], ah[i], b0h, b1h);
                    mma8(acc[i][j], al[i], b0h, b1h);
                    mma8(acc[i][j], ah[i], b0l, b1l);
                }
            }
        }
        __syncthreads();
    }
    #pragma unroll
    for (int i=0;i<4;i++){
        int row = m0 + (mtb+i)*16 + g;
        #pragma unroll
        for (int j=0;j<4;j++){
            int col = n0 + (ntb+j)*8 + 2*t;
            float bz0 = bias[col], bz1 = bias[col+1];
            #pragma unroll
            for (int h=0;h<2;h++){
                float v0 = acc[i][j][h*2+0] + bz0;
                float v1 = acc[i][j][h*2+1] + bz1;
                if (RELU){ v0=fmaxf(v0,0.f); v1=fmaxf(v1,0.f); }
                float* cp = C + (size_t)(row + h*8)*N + col;
                if (ACC){ cp[0]+=v0; cp[1]+=v1; }
                else    { cp[0]=v0;  cp[1]=v1; }
            }
        }
    }
}

template<bool RELU, bool ACC>
__global__ void __launch_bounds__(256) tgemm_kernel(const float* __restrict__ A,
                                                    const float* __restrict__ B,
                                                    const float* __restrict__ bias,
                                                    float* __restrict__ C,
                                                    int N, int K){
    __shared__ uint32_t As[4096], Bs[4096];
    tgemm_body<RELU,ACC>(A,B,bias,C,N,K, blockIdx.y*128, blockIdx.x*128, As, Bs);
}

__global__ void __launch_bounds__(256) tgemm_proj_kernel(const float* __restrict__ Av,
                                                         const float* __restrict__ Aa,
                                                         const float* __restrict__ Wv,
                                                         const float* __restrict__ Wa,
                                                         const float* __restrict__ bv,
                                                         const float* __restrict__ ba,
                                                         float* __restrict__ C){
    __shared__ uint32_t As[4096], Bs[4096];
    if (blockIdx.z == 0){
        tgemm_body<false,false>(Av, Wv, bv, C, 128, 1024, blockIdx.y*128, 0, As, Bs);
    } else {
        if (blockIdx.y >= NAROWS/128) return;
        tgemm_body<false,false>(Aa, Wa, ba, C + (size_t)NVROWS*CC, 128, 1024, blockIdx.y*128, 0, As, Bs);
    }
}

// SAGE gemm over 3 branches in one launch (z = branch), out to per-branch buffer
__global__ void __launch_bounds__(256) tgemm_sage_kernel(const float* __restrict__ bias){
    __shared__ uint32_t As[4096], Bs[4096];
    int z = blockIdx.z;
    tgemm_body<true,false>(g_CAT[z], g_WCAT, bias, g_SOUT[z], CC, 256,
                           blockIdx.y*128, 0, As, Bs);
}

__global__ void sum_out_kernel(float* __restrict__ out){
    int i = blockIdx.x*blockDim.x + threadIdx.x;
    if (i < NOUTR*CC) out[i] = g_SOUT[0][i] + g_SOUT[1][i] + g_SOUT[2][i];
}

// ------------------------- econv (warp per 4 nodes, pooled batches, FFMA2) -------------------------
// tsd: per-warp [4 edges][256 floats] with each t value duplicated (t at [2k],[2k+1])
template<int CNT>
__device__ __forceinline__ void kdotp(const float* __restrict__ W2, int lane,
                                      const float (*tsd)[256],
                                      unsigned long long acc[4][2]){
    const ulonglong2* W = (const ulonglong2*)W2;
    #pragma unroll 4
    for (int k = 0; k < CC; k++){
        ulonglong2 wv = __ldg(W + k*32 + lane);
        #pragma unroll
        for (int e = 0; e < CNT; e++){
            unsigned long long tt = *(const unsigned long long*)(tsd[e] + 2*k);
            fma2(acc[e][0], wv.x, tt);
            fma2(acc[e][1], wv.y, tt);
        }
    }
}

__device__ __forceinline__ void econv_body4(const float* __restrict__ UV, int ustride,
                                            int uoff, int voff,
                                            const float* __restrict__ W2,
                                            const float* __restrict__ b2,
                                            const int* __restrict__ browoff,
                                            const int* __restrict__ bsrc,
                                            float* __restrict__ Hout,
                                            const float* __restrict__ fcW,
                                            const float* __restrict__ fcb,
                                            float* __restrict__ ares,
                                            float (*tsd)[256], int n0, int lane){
    int o0 = browoff[n0], o1 = browoff[n0+1], o2 = browoff[n0+2],
        o3 = browoff[n0+3], o4 = browoff[n0+4];
    float4 m0 = make_float4(-1e30f,-1e30f,-1e30f,-1e30f);
    float4 m1 = m0, m2 = m0, m3 = m0;
    for (int p = o0; p < o4; p += 4){
        int cnt = min(4, o4 - p);
        int nls[4];
        #pragma unroll
        for (int e = 0; e < 4; e++){
            if (e >= cnt) break;
            int idx = p + e;
            int nl = (idx >= o1) + (idx >= o2) + (idx >= o3);
            nls[e] = nl;
            int s = bsrc[idx];
            float4 u = *(const float4*)(UV + (size_t)(n0+nl)*ustride + uoff + lane*4);
            float4 v = *(const float4*)(UV + (size_t)s*ustride + voff + lane*4);
            float4 t = f4relu(make_float4(u.x+v.x, u.y+v.y, u.z+v.z, u.w+v.w));
            *(float4*)&tsd[e][lane*8]     = make_float4(t.x, t.x, t.y, t.y);
            *(float4*)&tsd[e][lane*8 + 4] = make_float4(t.z, t.z, t.w, t.w);
        }
        __syncwarp();
        unsigned long long acc[4][2];
        #pragma unroll
        for (int e = 0; e < 4; e++){ acc[e][0] = 0ull; acc[e][1] = 0ull; }
        switch (cnt){
            case 1: kdotp<1>(W2, lane, (const float(*)[256])tsd, acc); break;
            case 2: kdotp<2>(W2, lane, (const float(*)[256])tsd, acc); break;
            case 3: kdotp<3>(W2, lane, (const float(*)[256])tsd, acc); break;
            default: kdotp<4>(W2, lane, (const float(*)[256])tsd, acc); break;
        }
        #pragma unroll
        for (int e = 0; e < 4; e++){
            if (e >= cnt) break;
            float2 a01, a23;
            memcpy(&a01, &acc[e][0], 8);
            memcpy(&a23, &acc[e][1], 8);
            float4 s4 = make_float4(a01.x, a01.y, a23.x, a23.y);
            int nl = nls[e];
            if (nl == 0) m0 = f4max(m0, s4);
            else if (nl == 1) m1 = f4max(m1, s4);
            else if (nl == 2) m2 = f4max(m2, s4);
            else m3 = f4max(m3, s4);
        }
        __syncwarp();
    }
    float4 bb = *(const float4*)(b2 + lane*4);
    float4 ms[4] = {m0, m1, m2, m3};
    int degs[4] = {o1-o0, o2-o1, o3-o2, o4-o3};
    #pragma unroll
    for (int i = 0; i < 4; i++){
        int node = n0 + i;
        float4 r;
        if (degs[i] > 0){
            float4 m = ms[i];
            r = f4relu(make_float4(m.x+bb.x, m.y+bb.y, m.z+bb.z, m.w+bb.w));
        } else {
            r = make_float4(0.f,0.f,0.f,0.f);
        }
        if (Hout) *(float4*)(Hout + (size_t)node*CC + lane*4) = r;
        if (ares){
            float part = r.x*fcW[lane*4] + r.y*fcW[lane*4+1] + r.z*fcW[lane*4+2] + r.w*fcW[lane*4+3];
            #pragma unroll
            for (int o = 16; o > 0; o >>= 1) part += __shfl_down_sync(0xffffffffu, part, o);
            if (lane == 0) ares[node] = part + fcb[0];
        }
    }
}

// ecA econv: list 0, fc fused -> ares. 8 warps/block, 4 nodes/warp.
__global__ void __launch_bounds__(256) econvA_kernel(const float* __restrict__ W2,
                                                     const float* __restrict__ b2,
                                                     const float* __restrict__ fcW,
                                                     const float* __restrict__ fcb){
    __shared__ float ts[8][4][256];
    int w = threadIdx.x >> 5, lane = threadIdx.x & 31;
    int n0 = (blockIdx.x * 8 + w) * 4;
    if (n0 >= NNODES) return;
    econv_body4(g_UVA, 256, 0, 128, W2, b2, g_browoff[0], g_bsrc[0],
                nullptr, fcW, fcb, g_ARES, ts[w], n0, lane);
}

// 3-branch econv in one launch (z = branch): lists 1..3, writes g_H[z]
__global__ void __launch_bounds__(256) econv3_kernel(const float* __restrict__ W2a,
                                                     const float* __restrict__ W2b,
                                                     const float* __restrict__ W2c,
                                                     const float* __restrict__ b2a,
                                                     const float* __restrict__ b2b,
                                                     const float* __restrict__ b2c){
    __shared__ float ts[8][4][256];
    int w = threadIdx.x >> 5, lane = threadIdx.x & 31;
    int n0 = (blockIdx.x * 8 + w) * 4;
    if (n0 >= NNODES) return;
    int z = blockIdx.z;
    const float* W2 = (z==0) ? W2a : (z==1) ? W2b : W2c;
    const float* b2 = (z==0) ? b2a : (z==1) ? b2b : b2c;
    econv_body4(g_UVB, 768, 256*z, 256*z + 128, W2, b2, g_browoff[1+z], g_bsrc[1+z],
                g_H[z], nullptr, nullptr, nullptr, ts[w], n0, lane);
}

// ------------------------- per-node graph kernels (masked lists) -------------------------
__global__ void vpa_kernel(){
    int w = threadIdx.x >> 5, lane = threadIdx.x & 31;
    int node = blockIdx.x * 8 + w;
    if (node >= NNODES) return;
    const float4* X4 = (const float4*)g_X;
    float4 xd = X4[(size_t)node*32 + lane];
    int p = g_browoff[4][node], pe = g_browoff[4][node+1];
    float4 o;
    if (p < pe){
        float4 m = make_float4(-1e30f,-1e30f,-1e30f,-1e30f);
        for (; p < pe; p++){
            float4 xs = X4[(size_t)g_bsrc[4][p]*32 + lane];
            m = f4max(m, make_float4(xd.x+xs.x, xd.y+xs.y, xd.z+xs.z, xd.w+xs.w));
        }
        o = f4relu(m);
    } else {
        o = make_float4(0.f,0.f,0.f,0.f);
    }
    ((float4*)g_XAG)[(size_t)node*32 + lane] = o;
}

__global__ void acv_kernel(){
    int w = threadIdx.x >> 5, lane = threadIdx.x & 31;
    int node = blockIdx.x * 8 + w;
    if (node >= NNODES) return;
    const float4* X4 = (const float4*)g_X;
    float4 xd = X4[(size_t)node*32 + lane];
    float4 acc = make_float4(0.f,0.f,0.f,0.f);
    int p = g_browoff[5][node], pe = g_browoff[5][node+1];
    for (; p < pe; p++){
        int s = g_bsrc[5][p];
        float wgt = g_ARES[s];
        float4 xs = X4[(size_t)s*32 + lane];
        acc.x += wgt*xs.x + xd.x;
        acc.y += wgt*xs.y + xd.y;
        acc.z += wgt*xs.z + xd.z;
        acc.w += wgt*xs.w + xd.w;
    }
    ((float4*)g_XV2)[(size_t)node*32 + lane] = f4relu(acc);
}

// CAT[z][r] = [ mean over branch list of H[z][src] | H[z][node] ], one launch z=3
__global__ void cat3_kernel(const int* __restrict__ spkp){
    int w = threadIdx.x >> 5, lane = threadIdx.x & 31;
    int r = blockIdx.x * 8 + w;
    if (r >= NOUTR) return;
    int z = blockIdx.z;
    int spk = spkp ? spkp[0] : 3;
    int node = (r >> 7) * spk * 128 + (r & 127);
    const float4* H4 = (const float4*)g_H[z];
    const int* browoff = g_browoff[1+z];
    const int* bsrc = g_bsrc[1+z];
    float4 s = make_float4(0.f,0.f,0.f,0.f);
    int p = browoff[node], pe = browoff[node+1];
    int cnt = pe - p;
    for (; p < pe; p++){
        float4 hs = H4[(size_t)bsrc[p]*32 + lane];
        s.x += hs.x; s.y += hs.y; s.z += hs.z; s.w += hs.w;
    }
    float inv = cnt ? 1.f/(float)cnt : 0.f;
    float4* C4 = (float4*)g_CAT[z];
    C4[(size_t)r*64 + lane]      = make_float4(s.x*inv, s.y*inv, s.z*inv, s.w*inv);
    C4[(size_t)r*64 + 32 + lane] = H4[(size_t)node*32 + lane];
}

// ------------------------- launch -------------------------
extern "C" void kernel_launch(void* const* d_in, const int* in_sizes, int n_in,
                              void* d_out, int out_size){
    const float* x_visual = (const float*)d_in[0];
    const float* x_audio  = (const float*)d_in[1];
    const float* W011 = (const float*)d_in[2];
    const float* b011 = (const float*)d_in[3];
    const float* W012 = (const float*)d_in[4];
    const float* b012 = (const float*)d_in[5];
    const float* ecA_W1 = (const float*)d_in[6];
    const float* ecA_b1 = (const float*)d_in[7];
    const float* ecA_W2 = (const float*)d_in[8];
    const float* ecA_b2 = (const float*)d_in[9];
    const float* ec1_W1 = (const float*)d_in[10];
    const float* ec1_b1 = (const float*)d_in[11];
    const float* ec1_W2 = (const float*)d_in[12];
    const float* ec1_b2 = (const float*)d_in[13];
    const float* ec2_W1 = (const float*)d_in[14];
    const float* ec2_b1 = (const float*)d_in[15];
    const float* ec2_W2 = (const float*)d_in[16];
    const float* ec2_b2 = (const float*)d_in[17];
    const float* ec3_W1 = (const float*)d_in[18];
    const float* ec3_b1 = (const float*)d_in[19];
    const float* ec3_W2 = (const float*)d_in[20];
    const float* ec3_b2 = (const float*)d_in[21];
    const float* sage_Wl = (const float*)d_in[22];
    const float* sage_bl = (const float*)d_in[23];
    const float* sage_Wr = (const float*)d_in[24];
    const float* fc_W = (const float*)d_in[25];
    const float* fc_b = (const float*)d_in[26];
    const int* edge_index = (const int*)d_in[27];
    const int* edge_attr  = (const int*)d_in[28];
    const int* speakers   = (n_in > 29) ? (const int*)d_in[29] : nullptr;
    float* out = (float*)d_out;

    float *pX, *pXAG, *pXV2, *pUVA, *pUVB;
    float *pWUVA, *pBUVA, *pWUVB, *pBUVB;
    cudaGetSymbolAddress((void**)&pX,    g_X);
    cudaGetSymbolAddress((void**)&pXAG,  g_XAG);
    cudaGetSymbolAddress((void**)&pXV2,  g_XV2);
    cudaGetSymbolAddress((void**)&pUVA,  g_UVA);
    cudaGetSymbolAddress((void**)&pUVB,  g_UVB);
    cudaGetSymbolAddress((void**)&pWUVA, g_WUVA);
    cudaGetSymbolAddress((void**)&pBUVA, g_BUVA);
    cudaGetSymbolAddress((void**)&pWUVB, g_WUVB);
    cudaGetSymbolAddress((void**)&pBUVB, g_BUVB);

    // masked edge-list build
    zero_cnt_kernel<<<NNODES/256, 256>>>();
    hist_kernel<<<NEDGES/256, 256>>>(edge_index, edge_attr);
    scan_kernel<<<1, 1024>>>();
    scatter_kernel<<<NEDGES/256, 256>>>(edge_index, edge_attr);

    // weight prep
    prep_kernel<<<(CC*768 + 255)/256, 256>>>(ecA_W1, ecA_b1, ec1_W1, ec1_b1,
                                             ec2_W1, ec2_b1, ec3_W1, ec3_b1,
                                             sage_Wl, sage_Wr);

    // input projections -> X (fused visual+audio, tensor cores)
    tgemm_proj_kernel<<<dim3(1, NVROWS/128, 2), 256>>>(x_visual, x_audio, W011, W012, b011, b012, pX);

    // xa_g
    vpa_kernel<<<NNODES/8, 256>>>();

    // u,v for ecA
    tgemm_kernel<false,false><<<dim3(2, NNODES/128), 256>>>(pXAG, pWUVA, pBUVA, pUVA, 256, CC);

    // ecA edge conv (fc fused) -> ares
    econvA_kernel<<<NNODES/32, 256>>>(ecA_W2, ecA_b2, fc_W, fc_b);

    // xv2
    acv_kernel<<<NNODES/8, 256>>>();

    // u,v for the 3 branches
    tgemm_kernel<false,false><<<dim3(6, NNODES/128), 256>>>(pXV2, pWUVB, pBUVB, pUVB, 768, CC);

    // 3 branch econvs in one launch
    econv3_kernel<<<dim3(NNODES/32, 1, 3), 256>>>(ec1_W2, ec2_W2, ec3_W2, ec1_b2, ec2_b2, ec3_b2);

    // cat for all 3 branches in one launch
    cat3_kernel<<<dim3(NOUTR/8, 1, 3), 256>>>(speakers);

    // SAGE gemm for all 3 branches in one launch, then sum
    tgemm_sage_kernel<<<dim3(1, NOUTR/128, 3), 256>>>(sage_bl);
    sum_out_kernel<<<(NOUTR*CC)/256, 256>>>(out);
}

// round 13
// speedup vs baseline: 1.2558x; 1.2558x over previous
#include <cuda_runtime.h>
#include <cstdint>

#define NNODES 32768
#define NEDGES 262144
#define CC 128
#define NOUTR 8192
#define NVROWS 24576
#define NAROWS 8192

// list ids: 0=ecA(-2) 1=b1[0,1] 2=b2[-1,0] 3=b3[-1,1] 4=vpa(-3) 5=acv(3)
#define NLISTS 6

// ------------------------- scratch (static device, no allocs) -------------------------
__device__ float g_X  [NNODES*CC];
__device__ float g_XAG[NNODES*CC];
__device__ float g_XV2[NNODES*CC];
__device__ float g_UVA[NNODES*256];
__device__ float g_UVB[NNODES*768];
__device__ float g_H  [3][NNODES*CC];
__device__ float g_CAT[3][NOUTR*256];
__device__ float g_SOUT[3][NOUTR*CC];
__device__ float g_ARES[NNODES];
__device__ int   g_bcnt[NLISTS][NNODES];
__device__ int   g_browoff[NLISTS][NNODES+1];
__device__ int   g_bcur[NLISTS][NNODES];
__device__ int   g_bsrc[NLISTS][NEDGES];
__device__ float g_WUVA[CC*256];
__device__ float g_BUVA[256];
__device__ float g_WUVB[CC*768];
__device__ float g_BUVB[768];
__device__ float g_WCAT[256*CC];

// ------------------------- small helpers -------------------------
__device__ __forceinline__ float4 f4max(float4 a, float4 b){
    return make_float4(fmaxf(a.x,b.x),fmaxf(a.y,b.y),fmaxf(a.z,b.z),fmaxf(a.w,b.w));
}
__device__ __forceinline__ float4 f4relu(float4 a){
    return make_float4(fmaxf(a.x,0.f),fmaxf(a.y,0.f),fmaxf(a.z,0.f),fmaxf(a.w,0.f));
}

// ------------------------- CSR build: 6 masked lists -------------------------
__global__ void zero_cnt_kernel(){
    int i = blockIdx.x*blockDim.x + threadIdx.x;
    if (i < NNODES){
        #pragma unroll
        for (int b = 0; b < NLISTS; b++) g_bcnt[b][i] = 0;
    }
}

__global__ void hist_kernel(const int* __restrict__ ei, const int* __restrict__ ea){
    int e = blockIdx.x*blockDim.x + threadIdx.x;
    if (e < NEDGES){
        int d = ei[NEDGES + e];
        int a = ea[e];
        if (a == -2)            atomicAdd(&g_bcnt[0][d], 1);
        if (a >= 0  && a <= 1)  atomicAdd(&g_bcnt[1][d], 1);
        if (a >= -1 && a <= 0)  atomicAdd(&g_bcnt[2][d], 1);
        if (a >= -1 && a <= 1)  atomicAdd(&g_bcnt[3][d], 1);
        if (a == -3)            atomicAdd(&g_bcnt[4][d], 1);
        if (a == 3)             atomicAdd(&g_bcnt[5][d], 1);
    }
}

__global__ void scan_kernel(){
    __shared__ int sh[1024];
    int tid = threadIdx.x;
    for (int b = 0; b < NLISTS; b++){
        int* cnt = g_bcnt[b];
        int* ro  = g_browoff[b];
        int* cur = g_bcur[b];
        int base = tid * 32;
        int s = 0;
        #pragma unroll
        for (int j = 0; j < 32; j++) s += cnt[base + j];
        sh[tid] = s;
        __syncthreads();
        int own = s;
        for (int off = 1; off < 1024; off <<= 1){
            int v = (tid >= off) ? sh[tid - off] : 0;
            __syncthreads();
            sh[tid] += v;
            __syncthreads();
        }
        int run = sh[tid] - own;
        for (int j = 0; j < 32; j++){
            ro[base + j] = run;
            cur[base + j] = run;
            run += cnt[base + j];
        }
        if (tid == 1023) ro[NNODES] = run;
        __syncthreads();
    }
}

__global__ void scatter_kernel(const int* __restrict__ ei, const int* __restrict__ ea){
    int e = blockIdx.x*blockDim.x + threadIdx.x;
    if (e < NEDGES){
        int d = ei[NEDGES + e];
        int s = ei[e];
        int a = ea[e];
        if (a == -2)           { int q = atomicAdd(&g_bcur[0][d], 1); g_bsrc[0][q] = s; }
        if (a >= 0  && a <= 1) { int q = atomicAdd(&g_bcur[1][d], 1); g_bsrc[1][q] = s; }
        if (a >= -1 && a <= 0) { int q = atomicAdd(&g_bcur[2][d], 1); g_bsrc[2][q] = s; }
        if (a >= -1 && a <= 1) { int q = atomicAdd(&g_bcur[3][d], 1); g_bsrc[3][q] = s; }
        if (a == -3)           { int q = atomicAdd(&g_bcur[4][d], 1); g_bsrc[4][q] = s; }
        if (a == 3)            { int q = atomicAdd(&g_bcur[5][d], 1); g_bsrc[5][q] = s; }
    }
}

// ------------------------- weight prep -------------------------
__global__ void prep_kernel(const float* __restrict__ ecA_W1, const float* __restrict__ ecA_b1,
                            const float* __restrict__ ec1_W1, const float* __restrict__ ec1_b1,
                            const float* __restrict__ ec2_W1, const float* __restrict__ ec2_b1,
                            const float* __restrict__ ec3_W1, const float* __restrict__ ec3_b1,
                            const float* __restrict__ Wl, const float* __restrict__ Wr){
    int id = blockIdx.x*blockDim.x + threadIdx.x;
    if (id < CC*256){
        int k = id >> 8, c = id & 255;
        float v;
        if (c < 128) v = ecA_W1[k*128 + c] - ecA_W1[(128+k)*128 + c];
        else         v = ecA_W1[(128+k)*128 + (c-128)];
        g_WUVA[k*256 + c] = v;
    }
    if (id < CC*768){
        int k = id / 768, c = id % 768;
        int b = c >> 8, cc = c & 255;
        const float* W1 = (b==0)? ec1_W1 : (b==1)? ec2_W1 : ec3_W1;
        float v;
        if (cc < 128) v = W1[k*128 + cc] - W1[(128+k)*128 + cc];
        else          v = W1[(128+k)*128 + (cc-128)];
        g_WUVB[k*768 + c] = v;
    }
    if (id < 256*CC){
        int k = id >> 7, c = id & 127;
        g_WCAT[id] = (k < 128) ? Wl[k*128 + c] : Wr[(k-128)*128 + c];
    }
    if (id < 256) g_BUVA[id] = (id < 128) ? ecA_b1[id] : 0.f;
    if (id < 768){
        int b = id >> 8, cc = id & 255;
        const float* bb = (b==0)? ec1_b1 : (b==1)? ec2_b1 : ec3_b1;
        g_BUVB[id] = (cc < 128) ? bb[cc] : 0.f;
    }
}

// ------------------------- TF32 tensor-core GEMM (single-pass) -------------------------
__device__ __forceinline__ uint32_t to_tf32(float x){
    uint32_t h; asm("cvt.rna.tf32.f32 %0, %1;" : "=r"(h) : "f"(x));
    return h;
}

__device__ __forceinline__ void mma8(float* c, const uint32_t* a, uint32_t b0, uint32_t b1){
    asm volatile("mma.sync.aligned.m16n8k8.row.col.f32.tf32.tf32.f32 "
        "{%0,%1,%2,%3},{%4,%5,%6,%7},{%8,%9},{%0,%1,%2,%3};"
        : "+f"(c[0]),"+f"(c[1]),"+f"(c[2]),"+f"(c[3])
        : "r"(a[0]),"r"(a[1]),"r"(a[2]),"r"(a[3]),"r"(b0),"r"(b1));
}

// Block tile 128x128, BK=16. 8 warps (2m x 4n), warp tile 64x32.
// As: 8 m-tiles x 2 kt x 4 words x 32 lanes = 2048 u32; Bs: 16 n-tiles x 2 kt x 2 words x 32 lanes = 2048 u32
template<bool RELU, bool ACC>
__device__ __forceinline__ void tgemm_body(const float* __restrict__ A,
                                           const float* __restrict__ B,
                                           const float* __restrict__ bias,
                                           float* __restrict__ C,
                                           int N, int K,
                                           int m0, int n0,
                                           uint32_t* As, uint32_t* Bs){
    int tid = threadIdx.x;
    int wid = tid>>5, lane = tid&31;
    int g = lane>>2, t = lane&3;
    int mtb = (wid>>2)*4;
    int ntb = (wid&3)*4;
    float acc[4][4][4];
    #pragma unroll
    for(int i=0;i<4;i++)
        #pragma unroll
        for(int j=0;j<4;j++)
            #pragma unroll
            for(int r=0;r<4;r++) acc[i][j][r]=0.f;

    for (int k0=0; k0<K; k0+=16){
        // ---- stage A (hi only): 512 lane-slots ----
        #pragma unroll
        for (int s0=0; s0<2; s0++){
            int s = tid + s0*256;
            int mt = s>>6, kt=(s>>5)&1, ln=s&31;
            int gg=ln>>2, tt=ln&3;
            const float* p  = A + (size_t)(m0+mt*16+gg)*K + (k0+kt*8+tt);
            const float* p8 = p + (size_t)8*K;
            uint32_t h0 = to_tf32(p[0]);
            uint32_t h2 = to_tf32(p[4]);
            uint32_t h1 = to_tf32(p8[0]);
            uint32_t h3 = to_tf32(p8[4]);
            uint32_t* d = As + (mt*2+kt)*128 + ln;
            d[0]=h0; d[32]=h1; d[64]=h2; d[96]=h3;
        }
        // ---- stage B (hi only): 1024 lane-slots ----
        #pragma unroll
        for (int s0=0; s0<4; s0++){
            int s = tid + s0*256;
            int nt = s>>6, kt=(s>>5)&1, ln=s&31;
            int gg=ln>>2, tt=ln&3;
            const float* p = B + (size_t)(k0+kt*8+tt)*N + (n0+nt*8+gg);
            uint32_t h0 = to_tf32(p[0]);
            uint32_t h1 = to_tf32(p[(size_t)4*N]);
            uint32_t* d = Bs + (nt*2+kt)*64 + ln;
            d[0]=h0; d[32]=h1;
        }
        __syncthreads();
        #pragma unroll
        for (int kt=0; kt<2; kt++){
            uint32_t ah[4][4];
            #pragma unroll
            for (int i=0;i<4;i++){
                const uint32_t* p = As + ((mtb+i)*2+kt)*128 + lane;
                #pragma unroll
                for (int r=0;r<4;r++) ah[i][r]=p[r*32];
            }
            #pragma unroll
            for (int j=0;j<4;j++){
                const uint32_t* p = Bs + ((ntb+j)*2+kt)*64 + lane;
                uint32_t b0h=p[0], b1h=p[32];
                #pragma unroll
                for (int i=0;i<4;i++)
                    mma8(acc[i][j], ah[i], b0h, b1h);
            }
        }
        __syncthreads();
    }
    #pragma unroll
    for (int i=0;i<4;i++){
        int row = m0 + (mtb+i)*16 + g;
        #pragma unroll
        for (int j=0;j<4;j++){
            int col = n0 + (ntb+j)*8 + 2*t;
            float bz0 = bias[col], bz1 = bias[col+1];
            #pragma unroll
            for (int h=0;h<2;h++){
                float v0 = acc[i][j][h*2+0] + bz0;
                float v1 = acc[i][j][h*2+1] + bz1;
                if (RELU){ v0=fmaxf(v0,0.f); v1=fmaxf(v1,0.f); }
                float* cp = C + (size_t)(row + h*8)*N + col;
                if (ACC){ cp[0]+=v0; cp[1]+=v1; }
                else    { cp[0]=v0;  cp[1]=v1; }
            }
        }
    }
}

template<bool RELU, bool ACC>
__global__ void __launch_bounds__(256) tgemm_kernel(const float* __restrict__ A,
                                                    const float* __restrict__ B,
                                                    const float* __restrict__ bias,
                                                    float* __restrict__ C,
                                                    int N, int K){
    __shared__ uint32_t As[2048], Bs[2048];
    tgemm_body<RELU,ACC>(A,B,bias,C,N,K, blockIdx.y*128, blockIdx.x*128, As, Bs);
}

__global__ void __launch_bounds__(256) tgemm_proj_kernel(const float* __restrict__ Av,
                                                         const float* __restrict__ Aa,
                                                         const float* __restrict__ Wv,
                                                         const float* __restrict__ Wa,
                                                         const float* __restrict__ bv,
                                                         const float* __restrict__ ba,
                                                         float* __restrict__ C){
    __shared__ uint32_t As[2048], Bs[2048];
    if (blockIdx.z == 0){
        tgemm_body<false,false>(Av, Wv, bv, C, 128, 1024, blockIdx.y*128, 0, As, Bs);
    } else {
        if (blockIdx.y >= NAROWS/128) return;
        tgemm_body<false,false>(Aa, Wa, ba, C + (size_t)NVROWS*CC, 128, 1024, blockIdx.y*128, 0, As, Bs);
    }
}

// SAGE gemm over 3 branches in one launch (z = branch), out to per-branch buffer
__global__ void __launch_bounds__(256) tgemm_sage_kernel(const float* __restrict__ bias){
    __shared__ uint32_t As[2048], Bs[2048];
    int z = blockIdx.z;
    tgemm_body<true,false>(g_CAT[z], g_WCAT, bias, g_SOUT[z], CC, 256,
                           blockIdx.y*128, 0, As, Bs);
}

__global__ void sum_out_kernel(float* __restrict__ out){
    int i = blockIdx.x*blockDim.x + threadIdx.x;
    if (i < NOUTR*CC) out[i] = g_SOUT[0][i] + g_SOUT[1][i] + g_SOUT[2][i];
}

// ------------------------- econv (warp per node, masked list) -------------------------
template<int CNT>
__device__ __forceinline__ void kdot(const float* __restrict__ W2, int lane,
                                     const float (*ts)[CC], float4 acc[4]){
    #pragma unroll 4
    for (int k = 0; k < CC; k++){
        float4 wv = __ldg((const float4*)(W2 + k*CC + lane*4));
        #pragma unroll
        for (int e = 0; e < CNT; e++){
            float t = ts[e][k];
            acc[e].x += wv.x * t;
            acc[e].y += wv.y * t;
            acc[e].z += wv.z * t;
            acc[e].w += wv.w * t;
        }
    }
}

__device__ __forceinline__ void econv_body(const float* __restrict__ UV, int ustride,
                                           int uoff, int voff,
                                           const float* __restrict__ W2,
                                           const float* __restrict__ b2,
                                           const int* __restrict__ browoff,
                                           const int* __restrict__ bsrc,
                                           float* __restrict__ Hout,
                                           const float* __restrict__ fcW,
                                           const float* __restrict__ fcb,
                                           float* __restrict__ ares,
                                           float (*tsw)[CC], int node, int lane){
    float4 u = *(const float4*)(UV + (size_t)node*ustride + uoff + lane*4);
    float4 macc = make_float4(-1e30f,-1e30f,-1e30f,-1e30f);
    int p = browoff[node], pe = browoff[node+1];
    bool found = (p < pe);
    while (p < pe){
        int cnt = min(4, pe - p);
        for (int e = 0; e < cnt; e++){
            int s = bsrc[p + e];
            float4 v = *(const float4*)(UV + (size_t)s*ustride + voff + lane*4);
            float4 t = f4relu(make_float4(u.x+v.x, u.y+v.y, u.z+v.z, u.w+v.w));
            *(float4*)&tsw[e][lane*4] = t;
        }
        p += cnt;
        __syncwarp();
        float4 acc[4];
        #pragma unroll
        for (int e = 0; e < 4; e++) acc[e] = make_float4(0.f,0.f,0.f,0.f);
        const float (*tw)[CC] = (const float (*)[CC])tsw;
        switch (cnt){
            case 1: kdot<1>(W2, lane, tw, acc); break;
            case 2: kdot<2>(W2, lane, tw, acc); break;
            case 3: kdot<3>(W2, lane, tw, acc); break;
            default: kdot<4>(W2, lane, tw, acc); break;
        }
        for (int e = 0; e < cnt; e++) macc = f4max(macc, acc[e]);
        __syncwarp();
    }
    float4 r;
    if (found){
        float4 bb = *(const float4*)(b2 + lane*4);
        r = f4relu(make_float4(macc.x+bb.x, macc.y+bb.y, macc.z+bb.z, macc.w+bb.w));
    } else {
        r = make_float4(0.f,0.f,0.f,0.f);
    }
    if (Hout) *(float4*)(Hout + (size_t)node*CC + lane*4) = r;
    if (ares){
        float part = r.x*fcW[lane*4] + r.y*fcW[lane*4+1] + r.z*fcW[lane*4+2] + r.w*fcW[lane*4+3];
        #pragma unroll
        for (int o = 16; o > 0; o >>= 1) part += __shfl_down_sync(0xffffffffu, part, o);
        if (lane == 0) ares[node] = part + fcb[0];
    }
}

// ecA econv: list 0, fc fused -> ares
__global__ void __launch_bounds__(256) econvA_kernel(const float* __restrict__ W2,
                                                     const float* __restrict__ b2,
                                                     const float* __restrict__ fcW,
                                                     const float* __restrict__ fcb){
    __shared__ float ts[8][4][CC];
    int w = threadIdx.x >> 5, lane = threadIdx.x & 31;
    int node = blockIdx.x * 8 + w;
    if (node >= NNODES) return;
    econv_body(g_UVA, 256, 0, 128, W2, b2, g_browoff[0], g_bsrc[0],
               nullptr, fcW, fcb, g_ARES, ts[w], node, lane);
}

// 3-branch econv in one launch (z = branch): lists 1..3, writes g_H[z]
__global__ void __launch_bounds__(256) econv3_kernel(const float* __restrict__ W2a,
                                                     const float* __restrict__ W2b,
                                                     const float* __restrict__ W2c,
                                                     const float* __restrict__ b2a,
                                                     const float* __restrict__ b2b,
                                                     const float* __restrict__ b2c){
    __shared__ float ts[8][4][CC];
    int w = threadIdx.x >> 5, lane = threadIdx.x & 31;
    int node = blockIdx.x * 8 + w;
    if (node >= NNODES) return;
    int z = blockIdx.z;
    const float* W2 = (z==0) ? W2a : (z==1) ? W2b : W2c;
    const float* b2 = (z==0) ? b2a : (z==1) ? b2b : b2c;
    econv_body(g_UVB, 768, 256*z, 256*z + 128, W2, b2, g_browoff[1+z], g_bsrc[1+z],
               g_H[z], nullptr, nullptr, nullptr, ts[w], node, lane);
}

// ------------------------- per-node graph kernels (masked lists) -------------------------
__global__ void vpa_kernel(){
    int w = threadIdx.x >> 5, lane = threadIdx.x & 31;
    int node = blockIdx.x * 8 + w;
    if (node >= NNODES) return;
    const float4* X4 = (const float4*)g_X;
    float4 xd = X4[(size_t)node*32 + lane];
    int p = g_browoff[4][node], pe = g_browoff[4][node+1];
    float4 o;
    if (p < pe){
        float4 m = make_float4(-1e30f,-1e30f,-1e30f,-1e30f);
        for (; p < pe; p++){
            float4 xs = X4[(size_t)g_bsrc[4][p]*32 + lane];
            m = f4max(m, make_float4(xd.x+xs.x, xd.y+xs.y, xd.z+xs.z, xd.w+xs.w));
        }
        o = f4relu(m);
    } else {
        o = make_float4(0.f,0.f,0.f,0.f);
    }
    ((float4*)g_XAG)[(size_t)node*32 + lane] = o;
}

__global__ void acv_kernel(){
    int w = threadIdx.x >> 5, lane = threadIdx.x & 31;
    int node = blockIdx.x * 8 + w;
    if (node >= NNODES) return;
    const float4* X4 = (const float4*)g_X;
    float4 xd = X4[(size_t)node*32 + lane];
    float4 acc = make_float4(0.f,0.f,0.f,0.f);
    int p = g_browoff[5][node], pe = g_browoff[5][node+1];
    for (; p < pe; p++){
        int s = g_bsrc[5][p];
        float wgt = g_ARES[s];
        float4 xs = X4[(size_t)s*32 + lane];
        acc.x += wgt*xs.x + xd.x;
        acc.y += wgt*xs.y + xd.y;
        acc.z += wgt*xs.z + xd.z;
        acc.w += wgt*xs.w + xd.w;
    }
    ((float4*)g_XV2)[(size_t)node*32 + lane] = f4relu(acc);
}

// CAT[z][r] = [ mean over branch list of H[z][src] | H[z][node] ], one launch z=3
__global__ void cat3_kernel(const int* __restrict__ spkp){
    int w = threadIdx.x >> 5, lane = threadIdx.x & 31;
    int r = blockIdx.x * 8 + w;
    if (r >= NOUTR) return;
    int z = blockIdx.z;
    int spk = spkp ? spkp[0] : 3;
    int node = (r >> 7) * spk * 128 + (r & 127);
    const float4* H4 = (const float4*)g_H[z];
    const int* browoff = g_browoff[1+z];
    const int* bsrc = g_bsrc[1+z];
    float4 s = make_float4(0.f,0.f,0.f,0.f);
    int p = browoff[node], pe = browoff[node+1];
    int cnt = pe - p;
    for (; p < pe; p++){
        float4 hs = H4[(size_t)bsrc[p]*32 + lane];
        s.x += hs.x; s.y += hs.y; s.z += hs.z; s.w += hs.w;
    }
    float inv = cnt ? 1.f/(float)cnt : 0.f;
    float4* C4 = (float4*)g_CAT[z];
    C4[(size_t)r*64 + lane]      = make_float4(s.x*inv, s.y*inv, s.z*inv, s.w*inv);
    C4[(size_t)r*64 + 32 + lane] = H4[(size_t)node*32 + lane];
}

// ------------------------- launch -------------------------
extern "C" void kernel_launch(void* const* d_in, const int* in_sizes, int n_in,
                              void* d_out, int out_size){
    const float* x_visual = (const float*)d_in[0];
    const float* x_audio  = (const float*)d_in[1];
    const float* W011 = (const float*)d_in[2];
    const float* b011 = (const float*)d_in[3];
    const float* W012 = (const float*)d_in[4];
    const float* b012 = (const float*)d_in[5];
    const float* ecA_W1 = (const float*)d_in[6];
    const float* ecA_b1 = (const float*)d_in[7];
    const float* ecA_W2 = (const float*)d_in[8];
    const float* ecA_b2 = (const float*)d_in[9];
    const float* ec1_W1 = (const float*)d_in[10];
    const float* ec1_b1 = (const float*)d_in[11];
    const float* ec1_W2 = (const float*)d_in[12];
    const float* ec1_b2 = (const float*)d_in[13];
    const float* ec2_W1 = (const float*)d_in[14];
    const float* ec2_b1 = (const float*)d_in[15];
    const float* ec2_W2 = (const float*)d_in[16];
    const float* ec2_b2 = (const float*)d_in[17];
    const float* ec3_W1 = (const float*)d_in[18];
    const float* ec3_b1 = (const float*)d_in[19];
    const float* ec3_W2 = (const float*)d_in[20];
    const float* ec3_b2 = (const float*)d_in[21];
    const float* sage_Wl = (const float*)d_in[22];
    const float* sage_bl = (const float*)d_in[23];
    const float* sage_Wr = (const float*)d_in[24];
    const float* fc_W = (const float*)d_in[25];
    const float* fc_b = (const float*)d_in[26];
    const int* edge_index = (const int*)d_in[27];
    const int* edge_attr  = (const int*)d_in[28];
    const int* speakers   = (n_in > 29) ? (const int*)d_in[29] : nullptr;
    float* out = (float*)d_out;

    float *pX, *pXAG, *pXV2, *pUVA, *pUVB;
    float *pWUVA, *pBUVA, *pWUVB, *pBUVB;
    cudaGetSymbolAddress((void**)&pX,    g_X);
    cudaGetSymbolAddress((void**)&pXAG,  g_XAG);
    cudaGetSymbolAddress((void**)&pXV2,  g_XV2);
    cudaGetSymbolAddress((void**)&pUVA,  g_UVA);
    cudaGetSymbolAddress((void**)&pUVB,  g_UVB);
    cudaGetSymbolAddress((void**)&pWUVA, g_WUVA);
    cudaGetSymbolAddress((void**)&pBUVA, g_BUVA);
    cudaGetSymbolAddress((void**)&pWUVB, g_WUVB);
    cudaGetSymbolAddress((void**)&pBUVB, g_BUVB);

    // masked edge-list build
    zero_cnt_kernel<<<NNODES/256, 256>>>();
    hist_kernel<<<NEDGES/256, 256>>>(edge_index, edge_attr);
    scan_kernel<<<1, 1024>>>();
    scatter_kernel<<<NEDGES/256, 256>>>(edge_index, edge_attr);

    // weight prep
    prep_kernel<<<(CC*768 + 255)/256, 256>>>(ecA_W1, ecA_b1, ec1_W1, ec1_b1,
                                             ec2_W1, ec2_b1, ec3_W1, ec3_b1,
                                             sage_Wl, sage_Wr);

    // input projections -> X (fused visual+audio, tensor cores)
    tgemm_proj_kernel<<<dim3(1, NVROWS/128, 2), 256>>>(x_visual, x_audio, W011, W012, b011, b012, pX);

    // xa_g
    vpa_kernel<<<NNODES/8, 256>>>();

    // u,v for ecA
    tgemm_kernel<false,false><<<dim3(2, NNODES/128), 256>>>(pXAG, pWUVA, pBUVA, pUVA, 256, CC);

    // ecA edge conv (fc fused) -> ares
    econvA_kernel<<<NNODES/8, 256>>>(ecA_W2, ecA_b2, fc_W, fc_b);

    // xv2
    acv_kernel<<<NNODES/8, 256>>>();

    // u,v for the 3 branches
    tgemm_kernel<false,false><<<dim3(6, NNODES/128), 256>>>(pXV2, pWUVB, pBUVB, pUVB, 768, CC);

    // 3 branch econvs in one launch
    econv3_kernel<<<dim3(NNODES/8, 1, 3), 256>>>(ec1_W2, ec2_W2, ec3_W2, ec1_b2, ec2_b2, ec3_b2);

    // cat for all 3 branches in one launch
    cat3_kernel<<<dim3(NOUTR/8, 1, 3), 256>>>(speakers);

    // SAGE gemm for all 3 branches in one launch, then sum
    tgemm_sage_kernel<<<dim3(1, NOUTR/128, 3), 256>>>(sage_bl);
    sum_out_kernel<<<(NOUTR*CC)/256, 256>>>(out);
}

// round 16
// speedup vs baseline: 1.3865x; 1.1041x over previous
#include <cuda_runtime.h>
#include <cstdint>

#define NNODES 32768
#define NEDGES 262144
#define CC 128
#define NOUTR 8192
#define NVROWS 24576
#define NAROWS 8192

// list ids: 0=ecA(-2) 1=b1[0,1] 2=b2[-1,0] 3=b3[-1,1] 4=vpa(-3) 5=acv(3)
#define NLISTS 6

// ------------------------- scratch (static device, no allocs) -------------------------
__device__ float g_X  [NNODES*CC];
__device__ float g_XAG[NNODES*CC];
__device__ float g_XV2[NNODES*CC];
__device__ float g_UVA[NNODES*256];
__device__ float g_UVB[NNODES*768];
__device__ float g_H  [3][NNODES*CC];      // branch H: written as encoded keys, decoded in place
__device__ unsigned g_HkA[NNODES*CC];      // ecA H keys
__device__ float g_CAT[3][NOUTR*256];
__device__ float g_SOUT[3][NOUTR*CC];
__device__ float g_ARES[NNODES];
__device__ int   g_bcnt[NLISTS][NNODES];
__device__ int   g_browoff[NLISTS][NNODES+1];
__device__ int   g_bcur[NLISTS][NNODES];
__device__ int   g_bsrc[NLISTS][NEDGES];
__device__ int   g_bdst[4][NEDGES];
__device__ float g_WUVA[CC*256];
__device__ float g_BUVA[256];
__device__ float g_WUVB[CC*768];
__device__ float g_BUVB[768];
__device__ float g_WCAT[256*CC];
__device__ uint32_t g_W2F[4][16384];       // pre-fragmented tf32 W2 per conv

// ------------------------- small helpers -------------------------
__device__ __forceinline__ float4 f4max(float4 a, float4 b){
    return make_float4(fmaxf(a.x,b.x),fmaxf(a.y,b.y),fmaxf(a.z,b.z),fmaxf(a.w,b.w));
}
__device__ __forceinline__ float4 f4relu(float4 a){
    return make_float4(fmaxf(a.x,0.f),fmaxf(a.y,0.f),fmaxf(a.z,0.f),fmaxf(a.w,0.f));
}
__device__ __forceinline__ unsigned fenc(float f){
    unsigned u = __float_as_uint(f);
    return (u & 0x80000000u) ? ~u : (u | 0x80000000u);
}
__device__ __forceinline__ float fdec(unsigned u){
    return __uint_as_float((u & 0x80000000u) ? (u & 0x7fffffffu) : ~u);
}

// ------------------------- CSR build: 6 masked lists -------------------------
__global__ void zero_cnt_kernel(){
    int i = blockIdx.x*blockDim.x + threadIdx.x;
    if (i < NNODES){
        #pragma unroll
        for (int b = 0; b < NLISTS; b++) g_bcnt[b][i] = 0;
    }
}

__global__ void hist_kernel(const int* __restrict__ ei, const int* __restrict__ ea){
    int e = blockIdx.x*blockDim.x + threadIdx.x;
    if (e < NEDGES){
        int d = ei[NEDGES + e];
        int a = ea[e];
        if (a == -2)            atomicAdd(&g_bcnt[0][d], 1);
        if (a >= 0  && a <= 1)  atomicAdd(&g_bcnt[1][d], 1);
        if (a >= -1 && a <= 0)  atomicAdd(&g_bcnt[2][d], 1);
        if (a >= -1 && a <= 1)  atomicAdd(&g_bcnt[3][d], 1);
        if (a == -3)            atomicAdd(&g_bcnt[4][d], 1);
        if (a == 3)             atomicAdd(&g_bcnt[5][d], 1);
    }
}

__global__ void scan_kernel(){
    __shared__ int sh[1024];
    int tid = threadIdx.x;
    for (int b = 0; b < NLISTS; b++){
        int* cnt = g_bcnt[b];
        int* ro  = g_browoff[b];
        int* cur = g_bcur[b];
        int base = tid * 32;
        int s = 0;
        #pragma unroll
        for (int j = 0; j < 32; j++) s += cnt[base + j];
        sh[tid] = s;
        __syncthreads();
        int own = s;
        for (int off = 1; off < 1024; off <<= 1){
            int v = (tid >= off) ? sh[tid - off] : 0;
            __syncthreads();
            sh[tid] += v;
            __syncthreads();
        }
        int run = sh[tid] - own;
        for (int j = 0; j < 32; j++){
            ro[base + j] = run;
            cur[base + j] = run;
            run += cnt[base + j];
        }
        if (tid == 1023) ro[NNODES] = run;
        __syncthreads();
    }
}

__global__ void scatter_kernel(const int* __restrict__ ei, const int* __restrict__ ea){
    int e = blockIdx.x*blockDim.x + threadIdx.x;
    if (e < NEDGES){
        int d = ei[NEDGES + e];
        int s = ei[e];
        int a = ea[e];
        if (a == -2)           { int q = atomicAdd(&g_bcur[0][d], 1); g_bsrc[0][q] = s; g_bdst[0][q] = d; }
        if (a >= 0  && a <= 1) { int q = atomicAdd(&g_bcur[1][d], 1); g_bsrc[1][q] = s; g_bdst[1][q] = d; }
        if (a >= -1 && a <= 0) { int q = atomicAdd(&g_bcur[2][d], 1); g_bsrc[2][q] = s; g_bdst[2][q] = d; }
        if (a >= -1 && a <= 1) { int q = atomicAdd(&g_bcur[3][d], 1); g_bsrc[3][q] = s; g_bdst[3][q] = d; }
        if (a == -3)           { int q = atomicAdd(&g_bcur[4][d], 1); g_bsrc[4][q] = s; }
        if (a == 3)            { int q = atomicAdd(&g_bcur[5][d], 1); g_bsrc[5][q] = s; }
    }
}

__global__ void initHk_kernel(){
    int i = blockIdx.x*blockDim.x + threadIdx.x;
    unsigned v = fenc(-1e30f);
    if (i < NNODES*CC) g_HkA[i] = v;
    if (i < 3*NNODES*CC) ((unsigned*)g_H)[i] = v;
}

// ------------------------- weight prep -------------------------
__global__ void prep_kernel(const float* __restrict__ ecA_W1, const float* __restrict__ ecA_b1,
                            const float* __restrict__ ec1_W1, const float* __restrict__ ec1_b1,
                            const float* __restrict__ ec2_W1, const float* __restrict__ ec2_b1,
                            const float* __restrict__ ec3_W1, const float* __restrict__ ec3_b1,
                            const float* __restrict__ Wl, const float* __restrict__ Wr){
    int id = blockIdx.x*blockDim.x + threadIdx.x;
    if (id < CC*256){
        int k = id >> 8, c = id & 255;
        float v;
        if (c < 128) v = ecA_W1[k*128 + c] - ecA_W1[(128+k)*128 + c];
        else         v = ecA_W1[(128+k)*128 + (c-128)];
        g_WUVA[k*256 + c] = v;
    }
    if (id < CC*768){
        int k = id / 768, c = id % 768;
        int b = c >> 8, cc = c & 255;
        const float* W1 = (b==0)? ec1_W1 : (b==1)? ec2_W1 : ec3_W1;
        float v;
        if (cc < 128) v = W1[k*128 + cc] - W1[(128+k)*128 + cc];
        else          v = W1[(128+k)*128 + (cc-128)];
        g_WUVB[k*768 + c] = v;
    }
    if (id < 256*CC){
        int k = id >> 7, c = id & 127;
        g_WCAT[id] = (k < 128) ? Wl[k*128 + c] : Wr[(k-128)*128 + c];
    }
    if (id < 256) g_BUVA[id] = (id < 128) ? ecA_b1[id] : 0.f;
    if (id < 768){
        int b = id >> 8, cc = id & 255;
        const float* bb = (b==0)? ec1_b1 : (b==1)? ec2_b1 : ec3_b1;
        g_BUVB[id] = (cc < 128) ? bb[cc] : 0.f;
    }
}

// ------------------------- TF32 helpers -------------------------
__device__ __forceinline__ uint32_t to_tf32(float x){
    uint32_t h; asm("cvt.rna.tf32.f32 %0, %1;" : "=r"(h) : "f"(x));
    return h;
}

__device__ __forceinline__ void mma8(float* c, const uint32_t* a, uint32_t b0, uint32_t b1){
    asm volatile("mma.sync.aligned.m16n8k8.row.col.f32.tf32.tf32.f32 "
        "{%0,%1,%2,%3},{%4,%5,%6,%7},{%8,%9},{%0,%1,%2,%3};"
        : "+f"(c[0]),"+f"(c[1]),"+f"(c[2]),"+f"(c[3])
        : "r"(a[0]),"r"(a[1]),"r"(a[2]),"r"(a[3]),"r"(b0),"r"(b1));
}

// W2 fragments: thread(lane) of fragment (kt,nt) holds b0=W2[kt*8+tt][nt*8+gg], b1=W2[kt*8+tt+4][nt*8+gg]
__global__ void prep_frag_kernel(const float* __restrict__ W2A, const float* __restrict__ W21,
                                 const float* __restrict__ W22, const float* __restrict__ W23){
    int id = blockIdx.x*blockDim.x + threadIdx.x;
    if (id >= 4*8192) return;
    int conv = id >> 13;
    int rem = id & 8191;
    int kt = rem >> 9;
    int nt = (rem >> 5) & 15;
    int lane = rem & 31;
    int gg = lane >> 2, tt = lane & 3;
    const float* W2 = (conv==0)?W2A:(conv==1)?W21:(conv==2)?W22:W23;
    g_W2F[conv][((kt*16+nt)*32+lane)*2 + 0] = to_tf32(W2[(kt*8+tt)*128 + nt*8+gg]);
    g_W2F[conv][((kt*16+nt)*32+lane)*2 + 1] = to_tf32(W2[(kt*8+tt+4)*128 + nt*8+gg]);
}

// ------------------------- TF32 tensor-core GEMM (single-pass, validated R13) -------------------------
template<bool RELU, bool ACC>
__device__ __forceinline__ void tgemm_body(const float* __restrict__ A,
                                           const float* __restrict__ B,
                                           const float* __restrict__ bias,
                                           float* __restrict__ C,
                                           int N, int K,
                                           int m0, int n0,
                                           uint32_t* As, uint32_t* Bs){
    int tid = threadIdx.x;
    int wid = tid>>5, lane = tid&31;
    int g = lane>>2, t = lane&3;
    int mtb = (wid>>2)*4;
    int ntb = (wid&3)*4;
    float acc[4][4][4];
    #pragma unroll
    for(int i=0;i<4;i++)
        #pragma unroll
        for(int j=0;j<4;j++)
            #pragma unroll
            for(int r=0;r<4;r++) acc[i][j][r]=0.f;

    for (int k0=0; k0<K; k0+=16){
        #pragma unroll
        for (int s0=0; s0<2; s0++){
            int s = tid + s0*256;
            int mt = s>>6, kt=(s>>5)&1, ln=s&31;
            int gg=ln>>2, tt=ln&3;
            const float* p  = A + (size_t)(m0+mt*16+gg)*K + (k0+kt*8+tt);
            const float* p8 = p + (size_t)8*K;
            uint32_t h0 = to_tf32(p[0]);
            uint32_t h2 = to_tf32(p[4]);
            uint32_t h1 = to_tf32(p8[0]);
            uint32_t h3 = to_tf32(p8[4]);
            uint32_t* d = As + (mt*2+kt)*128 + ln;
            d[0]=h0; d[32]=h1; d[64]=h2; d[96]=h3;
        }
        #pragma unroll
        for (int s0=0; s0<4; s0++){
            int s = tid + s0*256;
            int nt = s>>6, kt=(s>>5)&1, ln=s&31;
            int gg=ln>>2, tt=ln&3;
            const float* p = B + (size_t)(k0+kt*8+tt)*N + (n0+nt*8+gg);
            uint32_t h0 = to_tf32(p[0]);
            uint32_t h1 = to_tf32(p[(size_t)4*N]);
            uint32_t* d = Bs + (nt*2+kt)*64 + ln;
            d[0]=h0; d[32]=h1;
        }
        __syncthreads();
        #pragma unroll
        for (int kt=0; kt<2; kt++){
            uint32_t ah[4][4];
            #pragma unroll
            for (int i=0;i<4;i++){
                const uint32_t* p = As + ((mtb+i)*2+kt)*128 + lane;
                #pragma unroll
                for (int r=0;r<4;r++) ah[i][r]=p[r*32];
            }
            #pragma unroll
            for (int j=0;j<4;j++){
                const uint32_t* p = Bs + ((ntb+j)*2+kt)*64 + lane;
                uint32_t b0h=p[0], b1h=p[32];
                #pragma unroll
                for (int i=0;i<4;i++)
                    mma8(acc[i][j], ah[i], b0h, b1h);
            }
        }
        __syncthreads();
    }
    #pragma unroll
    for (int i=0;i<4;i++){
        int row = m0 + (mtb+i)*16 + g;
        #pragma unroll
        for (int j=0;j<4;j++){
            int col = n0 + (ntb+j)*8 + 2*t;
            float bz0 = bias[col], bz1 = bias[col+1];
            #pragma unroll
            for (int h=0;h<2;h++){
                float v0 = acc[i][j][h*2+0] + bz0;
                float v1 = acc[i][j][h*2+1] + bz1;
                if (RELU){ v0=fmaxf(v0,0.f); v1=fmaxf(v1,0.f); }
                float* cp = C + (size_t)(row + h*8)*N + col;
                if (ACC){ cp[0]+=v0; cp[1]+=v1; }
                else    { cp[0]=v0;  cp[1]=v1; }
            }
        }
    }
}

template<bool RELU, bool ACC>
__global__ void __launch_bounds__(256) tgemm_kernel(const float* __restrict__ A,
                                                    const float* __restrict__ B,
                                                    const float* __restrict__ bias,
                                                    float* __restrict__ C,
                                                    int N, int K){
    __shared__ uint32_t As[2048], Bs[2048];
    tgemm_body<RELU,ACC>(A,B,bias,C,N,K, blockIdx.y*128, blockIdx.x*128, As, Bs);
}

__global__ void __launch_bounds__(256) tgemm_proj_kernel(const float* __restrict__ Av,
                                                         const float* __restrict__ Aa,
                                                         const float* __restrict__ Wv,
                                                         const float* __restrict__ Wa,
                                                         const float* __restrict__ bv,
                                                         const float* __restrict__ ba,
                                                         float* __restrict__ C){
    __shared__ uint32_t As[2048], Bs[2048];
    if (blockIdx.z == 0){
        tgemm_body<false,false>(Av, Wv, bv, C, 128, 1024, blockIdx.y*128, 0, As, Bs);
    } else {
        if (blockIdx.y >= NAROWS/128) return;
        tgemm_body<false,false>(Aa, Wa, ba, C + (size_t)NVROWS*CC, 128, 1024, blockIdx.y*128, 0, As, Bs);
    }
}

__global__ void __launch_bounds__(256) tgemm_sage_kernel(const float* __restrict__ bias){
    __shared__ uint32_t As[2048], Bs[2048];
    int z = blockIdx.z;
    tgemm_body<true,false>(g_CAT[z], g_WCAT, bias, g_SOUT[z], CC, 256,
                           blockIdx.y*128, 0, As, Bs);
}

__global__ void sum_out_kernel(float* __restrict__ out){
    int i = blockIdx.x*blockDim.x + threadIdx.x;
    if (i < NOUTR*CC) out[i] = g_SOUT[0][i] + g_SOUT[1][i] + g_SOUT[2][i];
}

// ------------------------- econv via warp-level tensor-core MMA -------------------------
// Warp-private tile: ts[16][132] (pad 4 -> conflict-free). 16 edges per tile, grid-stride.
__device__ __forceinline__ void econv_mma_body(const float* __restrict__ UV, int ustride,
                                               int uoff, int voff,
                                               const uint32_t* __restrict__ W2F,
                                               const int* __restrict__ browoff,
                                               const int* __restrict__ bsrc,
                                               const int* __restrict__ bdst,
                                               unsigned* __restrict__ Hk,
                                               float* ts, int warpGlobal, int warpStride, int lane){
    int cnt = browoff[NNODES];
    int g = lane >> 2, t4 = lane & 3;
    for (int tile = warpGlobal; tile*16 < cnt; tile += warpStride){
        int base = tile*16;
        int tcnt = min(16, cnt - base);
        int eidx = base + lane;
        int sE = 0, dE = 0;
        if (lane < 16 && eidx < cnt){ sE = bsrc[eidx]; dE = bdst[eidx]; }
        // ---- gather T[e,:] = relu(u[dst]+v[src]) ----
        #pragma unroll 4
        for (int e = 0; e < 16; e++){
            float4 tv = make_float4(0.f,0.f,0.f,0.f);
            if (e < tcnt){
                int s = __shfl_sync(0xffffffffu, sE, e);
                int d = __shfl_sync(0xffffffffu, dE, e);
                float4 u = *(const float4*)(UV + (size_t)d*ustride + uoff + lane*4);
                float4 v = *(const float4*)(UV + (size_t)s*ustride + voff + lane*4);
                tv = f4relu(make_float4(u.x+v.x, u.y+v.y, u.z+v.z, u.w+v.w));
            }
            *(float4*)(ts + e*132 + lane*4) = tv;
        }
        __syncwarp();
        // ---- S = T @ W2 via mma (16x128x128) ----
        float acc[16][4];
        #pragma unroll
        for (int nt = 0; nt < 16; nt++){
            acc[nt][0]=0.f; acc[nt][1]=0.f; acc[nt][2]=0.f; acc[nt][3]=0.f;
        }
        #pragma unroll
        for (int kt = 0; kt < 16; kt++){
            uint32_t a[4];
            a[0] = to_tf32(ts[(size_t)g*132      + kt*8 + t4    ]);
            a[1] = to_tf32(ts[(size_t)(g+8)*132  + kt*8 + t4    ]);
            a[2] = to_tf32(ts[(size_t)g*132      + kt*8 + t4 + 4]);
            a[3] = to_tf32(ts[(size_t)(g+8)*132  + kt*8 + t4 + 4]);
            uint2 bf[16];
            #pragma unroll
            for (int nt = 0; nt < 16; nt++)
                bf[nt] = __ldg((const uint2*)(W2F + ((size_t)(kt*16+nt)*32 + lane)*2));
            #pragma unroll
            for (int nt = 0; nt < 16; nt++)
                mma8(acc[nt], a, bf[nt].x, bf[nt].y);
        }
        __syncwarp();
        // ---- write S back into ts (C fragment: rows g,g+8; cols nt*8+2t4,+1) ----
        #pragma unroll
        for (int nt = 0; nt < 16; nt++){
            *(float2*)(ts + (size_t)g*132     + nt*8 + 2*t4) = make_float2(acc[nt][0], acc[nt][1]);
            *(float2*)(ts + (size_t)(g+8)*132 + nt*8 + 2*t4) = make_float2(acc[nt][2], acc[nt][3]);
        }
        __syncwarp();
        // ---- segmented max over dst runs ----
        int r = 0;
        while (r < tcnt){
            int d = __shfl_sync(0xffffffffu, dE, r);
            int r2 = r + 1;
            while (r2 < tcnt && __shfl_sync(0xffffffffu, dE, r2) == d) r2++;
            float4 m = *(const float4*)(ts + (size_t)r*132 + lane*4);
            for (int p = r+1; p < r2; p++)
                m = f4max(m, *(const float4*)(ts + (size_t)p*132 + lane*4));
            bool headIn = (r > 0) || (browoff[d] == base);
            bool tailIn = (r2 < tcnt) || (base + tcnt == cnt) || (browoff[d+1] == base + 16);
            unsigned* hp = Hk + (size_t)d*CC + lane*4;
            unsigned e0 = fenc(m.x), e1 = fenc(m.y), e2 = fenc(m.z), e3 = fenc(m.w);
            if (headIn && tailIn){
                hp[0]=e0; hp[1]=e1; hp[2]=e2; hp[3]=e3;
            } else {
                atomicMax(hp+0, e0); atomicMax(hp+1, e1);
                atomicMax(hp+2, e2); atomicMax(hp+3, e3);
            }
            r = r2;
        }
        __syncwarp();
    }
}

__global__ void __launch_bounds__(256) econvA_mma_kernel(){
    extern __shared__ float sts[];
    int w = threadIdx.x >> 5, lane = threadIdx.x & 31;
    econv_mma_body(g_UVA, 256, 0, 128, g_W2F[0],
                   g_browoff[0], g_bsrc[0], g_bdst[0], g_HkA,
                   sts + (size_t)w*16*132, blockIdx.x*8 + w, gridDim.x*8, lane);
}

__global__ void __launch_bounds__(256) econv3_mma_kernel(){
    extern __shared__ float sts[];
    int w = threadIdx.x >> 5, lane = threadIdx.x & 31;
    int z = blockIdx.z;
    econv_mma_body(g_UVB, 768, 256*z, 256*z + 128, g_W2F[1+z],
                   g_browoff[1+z], g_bsrc[1+z], g_bdst[1+z], (unsigned*)g_H[z],
                   sts + (size_t)w*16*132, blockIdx.x*8 + w, gridDim.x*8, lane);
}

// decode HkA -> relu(max+b2) (empty->0) -> fc dot -> ares
__global__ void finalizeA_kernel(const float* __restrict__ b2,
                                 const float* __restrict__ fcW,
                                 const float* __restrict__ fcb){
    int w = threadIdx.x >> 5, lane = threadIdx.x & 31;
    int node = blockIdx.x * 8 + w;
    if (node >= NNODES) return;
    unsigned* hp = g_HkA + (size_t)node*CC + lane*4;
    float f0 = fdec(hp[0]), f1 = fdec(hp[1]), f2 = fdec(hp[2]), f3 = fdec(hp[3]);
    float4 r;
    if (f0 < -5e29f){
        r = make_float4(0.f,0.f,0.f,0.f);
    } else {
        float4 bb = *(const float4*)(b2 + lane*4);
        r = f4relu(make_float4(f0+bb.x, f1+bb.y, f2+bb.z, f3+bb.w));
    }
    float part = r.x*fcW[lane*4] + r.y*fcW[lane*4+1] + r.z*fcW[lane*4+2] + r.w*fcW[lane*4+3];
    #pragma unroll
    for (int o = 16; o > 0; o >>= 1) part += __shfl_down_sync(0xffffffffu, part, o);
    if (lane == 0) g_ARES[node] = part + fcb[0];
}

// decode g_H[z] keys in place -> float H (empty->0, else relu(max+b2z))
__global__ void finalize3_kernel(const float* __restrict__ b2a,
                                 const float* __restrict__ b2b,
                                 const float* __restrict__ b2c){
    int w = threadIdx.x >> 5, lane = threadIdx.x & 31;
    int node = blockIdx.x * 8 + w;
    if (node >= NNODES) return;
    int z = blockIdx.z;
    const float* b2 = (z==0) ? b2a : (z==1) ? b2b : b2c;
    unsigned* hp = (unsigned*)g_H[z] + (size_t)node*CC + lane*4;
    float f0 = fdec(hp[0]), f1 = fdec(hp[1]), f2 = fdec(hp[2]), f3 = fdec(hp[3]);
    float4 r;
    if (f0 < -5e29f){
        r = make_float4(0.f,0.f,0.f,0.f);
    } else {
        float4 bb = *(const float4*)(b2 + lane*4);
        r = f4relu(make_float4(f0+bb.x, f1+bb.y, f2+bb.z, f3+bb.w));
    }
    float* fp = (float*)hp;
    fp[0]=r.x; fp[1]=r.y; fp[2]=r.z; fp[3]=r.w;
}

// ------------------------- per-node graph kernels (masked lists) -------------------------
__global__ void vpa_kernel(){
    int w = threadIdx.x >> 5, lane = threadIdx.x & 31;
    int node = blockIdx.x * 8 + w;
    if (node >= NNODES) return;
    const float4* X4 = (const float4*)g_X;
    float4 xd = X4[(size_t)node*32 + lane];
    int p = g_browoff[4][node], pe = g_browoff[4][node+1];
    float4 o;
    if (p < pe){
        float4 m = make_float4(-1e30f,-1e30f,-1e30f,-1e30f);
        for (; p < pe; p++){
            float4 xs = X4[(size_t)g_bsrc[4][p]*32 + lane];
            m = f4max(m, make_float4(xd.x+xs.x, xd.y+xs.y, xd.z+xs.z, xd.w+xs.w));
        }
        o = f4relu(m);
    } else {
        o = make_float4(0.f,0.f,0.f,0.f);
    }
    ((float4*)g_XAG)[(size_t)node*32 + lane] = o;
}

__global__ void acv_kernel(){
    int w = threadIdx.x >> 5, lane = threadIdx.x & 31;
    int node = blockIdx.x * 8 + w;
    if (node >= NNODES) return;
    const float4* X4 = (const float4*)g_X;
    float4 xd = X4[(size_t)node*32 + lane];
    float4 acc = make_float4(0.f,0.f,0.f,0.f);
    int p = g_browoff[5][node], pe = g_browoff[5][node+1];
    for (; p < pe; p++){
        int s = g_bsrc[5][p];
        float wgt = g_ARES[s];
        float4 xs = X4[(size_t)s*32 + lane];
        acc.x += wgt*xs.x + xd.x;
        acc.y += wgt*xs.y + xd.y;
        acc.z += wgt*xs.z + xd.z;
        acc.w += wgt*xs.w + xd.w;
    }
    ((float4*)g_XV2)[(size_t)node*32 + lane] = f4relu(acc);
}

__global__ void cat3_kernel(const int* __restrict__ spkp){
    int w = threadIdx.x >> 5, lane = threadIdx.x & 31;
    int r = blockIdx.x * 8 + w;
    if (r >= NOUTR) return;
    int z = blockIdx.z;
    int spk = spkp ? spkp[0] : 3;
    int node = (r >> 7) * spk * 128 + (r & 127);
    const float4* H4 = (const float4*)g_H[z];
    const int* browoff = g_browoff[1+z];
    const int* bsrc = g_bsrc[1+z];
    float4 s = make_float4(0.f,0.f,0.f,0.f);
    int p = browoff[node], pe = browoff[node+1];
    int cnt = pe - p;
    for (; p < pe; p++){
        float4 hs = H4[(size_t)bsrc[p]*32 + lane];
        s.x += hs.x; s.y += hs.y; s.z += hs.z; s.w += hs.w;
    }
    float inv = cnt ? 1.f/(float)cnt : 0.f;
    float4* C4 = (float4*)g_CAT[z];
    C4[(size_t)r*64 + lane]      = make_float4(s.x*inv, s.y*inv, s.z*inv, s.w*inv);
    C4[(size_t)r*64 + 32 + lane] = H4[(size_t)node*32 + lane];
}

// ------------------------- launch -------------------------
extern "C" void kernel_launch(void* const* d_in, const int* in_sizes, int n_in,
                              void* d_out, int out_size){
    const float* x_visual = (const float*)d_in[0];
    const float* x_audio  = (const float*)d_in[1];
    const float* W011 = (const float*)d_in[2];
    const float* b011 = (const float*)d_in[3];
    const float* W012 = (const float*)d_in[4];
    const float* b012 = (const float*)d_in[5];
    const float* ecA_W1 = (const float*)d_in[6];
    const float* ecA_b1 = (const float*)d_in[7];
    const float* ecA_W2 = (const float*)d_in[8];
    const float* ecA_b2 = (const float*)d_in[9];
    const float* ec1_W1 = (const float*)d_in[10];
    const float* ec1_b1 = (const float*)d_in[11];
    const float* ec1_W2 = (const float*)d_in[12];
    const float* ec1_b2 = (const float*)d_in[13];
    const float* ec2_W1 = (const float*)d_in[14];
    const float* ec2_b1 = (const float*)d_in[15];
    const float* ec2_W2 = (const float*)d_in[16];
    const float* ec2_b2 = (const float*)d_in[17];
    const float* ec3_W1 = (const float*)d_in[18];
    const float* ec3_b1 = (const float*)d_in[19];
    const float* ec3_W2 = (const float*)d_in[20];
    const float* ec3_b2 = (const float*)d_in[21];
    const float* sage_Wl = (const float*)d_in[22];
    const float* sage_bl = (const float*)d_in[23];
    const float* sage_Wr = (const float*)d_in[24];
    const float* fc_W = (const float*)d_in[25];
    const float* fc_b = (const float*)d_in[26];
    const int* edge_index = (const int*)d_in[27];
    const int* edge_attr  = (const int*)d_in[28];
    const int* speakers   = (n_in > 29) ? (const int*)d_in[29] : nullptr;
    float* out = (float*)d_out;

    float *pX, *pXAG, *pXV2, *pUVA, *pUVB;
    float *pWUVA, *pBUVA, *pWUVB, *pBUVB;
    cudaGetSymbolAddress((void**)&pX,    g_X);
    cudaGetSymbolAddress((void**)&pXAG,  g_XAG);
    cudaGetSymbolAddress((void**)&pXV2,  g_XV2);
    cudaGetSymbolAddress((void**)&pUVA,  g_UVA);
    cudaGetSymbolAddress((void**)&pUVB,  g_UVB);
    cudaGetSymbolAddress((void**)&pWUVA, g_WUVA);
    cudaGetSymbolAddress((void**)&pBUVA, g_BUVA);
    cudaGetSymbolAddress((void**)&pWUVB, g_WUVB);
    cudaGetSymbolAddress((void**)&pBUVB, g_BUVB);

    static bool attr_done = false;
    if (!attr_done){
        cudaFuncSetAttribute(econvA_mma_kernel, cudaFuncAttributeMaxDynamicSharedMemorySize, 8*16*132*4);
        cudaFuncSetAttribute(econv3_mma_kernel, cudaFuncAttributeMaxDynamicSharedMemorySize, 8*16*132*4);
        attr_done = true;
    }
    const int ECONV_SMEM = 8*16*132*4;  // 67584 B

    // masked edge-list build
    zero_cnt_kernel<<<NNODES/256, 256>>>();
    hist_kernel<<<NEDGES/256, 256>>>(edge_index, edge_attr);
    scan_kernel<<<1, 1024>>>();
    scatter_kernel<<<NEDGES/256, 256>>>(edge_index, edge_attr);

    // init H keys (all 4 convs)
    initHk_kernel<<<(3*NNODES*CC)/256, 256>>>();

    // weight prep
    prep_kernel<<<(CC*768 + 255)/256, 256>>>(ecA_W1, ecA_b1, ec1_W1, ec1_b1,
                                             ec2_W1, ec2_b1, ec3_W1, ec3_b1,
                                             sage_Wl, sage_Wr);
    prep_frag_kernel<<<(4*8192)/256, 256>>>(ecA_W2, ec1_W2, ec2_W2, ec3_W2);

    // input projections -> X
    tgemm_proj_kernel<<<dim3(1, NVROWS/128, 2), 256>>>(x_visual, x_audio, W011, W012, b011, b012, pX);

    // xa_g
    vpa_kernel<<<NNODES/8, 256>>>();

    // u,v for ecA
    tgemm_kernel<false,false><<<dim3(2, NNODES/128), 256>>>(pXAG, pWUVA, pBUVA, pUVA, 256, CC);

    // ecA edge conv (tensor-core) -> finalize (fc fused) -> ares
    econvA_mma_kernel<<<512, 256, ECONV_SMEM>>>();
    finalizeA_kernel<<<NNODES/8, 256>>>(ecA_b2, fc_W, fc_b);

    // xv2
    acv_kernel<<<NNODES/8, 256>>>();

    // u,v for the 3 branches
    tgemm_kernel<false,false><<<dim3(6, NNODES/128), 256>>>(pXV2, pWUVB, pBUVB, pUVB, 768, CC);

    // 3 branch econvs (tensor-core) + finalize
    econv3_mma_kernel<<<dim3(512, 1, 3), 256, ECONV_SMEM>>>();
    finalize3_kernel<<<dim3(NNODES/8, 1, 3), 256>>>(ec1_b2, ec2_b2, ec3_b2);

    // cat for all 3 branches
    cat3_kernel<<<dim3(NOUTR/8, 1, 3), 256>>>(speakers);

    // SAGE gemm + sum
    tgemm_sage_kernel<<<dim3(1, NOUTR/128, 3), 256>>>(sage_bl);
    sum_out_kernel<<<(NOUTR*CC)/256, 256>>>(out);
}

// round 17
// speedup vs baseline: 1.6855x; 1.2156x over previous
#include <cuda_runtime.h>
#include <cstdint>

#define NNODES 32768
#define NEDGES 262144
#define CC 128
#define NOUTR 8192
#define NVROWS 24576
#define NAROWS 8192

// list ids: 0=ecA(-2) 1=b1[0,1] 2=b2[-1,0] 3=b3[-1,1] 4=vpa(-3) 5=acv(3)
#define NLISTS 6

// ------------------------- scratch (static device, no allocs) -------------------------
__device__ float g_X  [NNODES*CC];
__device__ float g_XAG[NNODES*CC];
__device__ float g_XV2[NNODES*CC];
__device__ float g_UVA[NNODES*256];
__device__ float g_UVB[NNODES*768];
__device__ float g_H  [3][NNODES*CC];      // branch H: written as encoded keys, decoded in place
__device__ unsigned g_HkA[NNODES*CC];      // ecA H keys
__device__ float g_CAT[3][NOUTR*256];
__device__ float g_SOUT[3][NOUTR*CC];
__device__ float g_ARES[NNODES];
__device__ int   g_bcnt[NLISTS][NNODES];
__device__ int   g_browoff[NLISTS][NNODES+1];
__device__ int   g_bcur[NLISTS][NNODES];
__device__ int   g_bsrc[NLISTS][NEDGES];
__device__ int   g_bdst[4][NEDGES];
__device__ float g_WUVA[CC*256];
__device__ float g_BUVA[256];
__device__ float g_WUVB[CC*768];
__device__ float g_BUVB[768];
__device__ float g_WCAT[256*CC];
__device__ uint32_t g_W2F[4][16384];       // pre-fragmented tf32 W2 per conv (uint4-paired)

// ------------------------- small helpers -------------------------
__device__ __forceinline__ float4 f4max(float4 a, float4 b){
    return make_float4(fmaxf(a.x,b.x),fmaxf(a.y,b.y),fmaxf(a.z,b.z),fmaxf(a.w,b.w));
}
__device__ __forceinline__ float4 f4relu(float4 a){
    return make_float4(fmaxf(a.x,0.f),fmaxf(a.y,0.f),fmaxf(a.z,0.f),fmaxf(a.w,0.f));
}
__device__ __forceinline__ unsigned fenc(float f){
    unsigned u = __float_as_uint(f);
    return (u & 0x80000000u) ? ~u : (u | 0x80000000u);
}
__device__ __forceinline__ float fdec(unsigned u){
    return __uint_as_float((u & 0x80000000u) ? (u & 0x7fffffffu) : ~u);
}

// ------------------------- init (bcnt zero + H keys) -------------------------
__global__ void initzero_kernel(){
    int i = blockIdx.x*blockDim.x + threadIdx.x;
    unsigned v = fenc(-1e30f);
    if (i < NNODES){
        #pragma unroll
        for (int b = 0; b < NLISTS; b++) g_bcnt[b][i] = 0;
    }
    if (i < NNODES*CC) g_HkA[i] = v;
    if (i < 3*NNODES*CC) ((unsigned*)g_H)[i] = v;
}

// ------------------------- CSR build: 6 masked lists -------------------------
__global__ void hist_kernel(const int* __restrict__ ei, const int* __restrict__ ea){
    int e = blockIdx.x*blockDim.x + threadIdx.x;
    if (e < NEDGES){
        int d = ei[NEDGES + e];
        int a = ea[e];
        if (a == -2)            atomicAdd(&g_bcnt[0][d], 1);
        if (a >= 0  && a <= 1)  atomicAdd(&g_bcnt[1][d], 1);
        if (a >= -1 && a <= 0)  atomicAdd(&g_bcnt[2][d], 1);
        if (a >= -1 && a <= 1)  atomicAdd(&g_bcnt[3][d], 1);
        if (a == -3)            atomicAdd(&g_bcnt[4][d], 1);
        if (a == 3)             atomicAdd(&g_bcnt[5][d], 1);
    }
}

__global__ void scan_kernel(){
    __shared__ int sh[1024];
    int tid = threadIdx.x;
    for (int b = 0; b < NLISTS; b++){
        int* cnt = g_bcnt[b];
        int* ro  = g_browoff[b];
        int* cur = g_bcur[b];
        int base = tid * 32;
        int s = 0;
        #pragma unroll
        for (int j = 0; j < 32; j++) s += cnt[base + j];
        sh[tid] = s;
        __syncthreads();
        int own = s;
        for (int off = 1; off < 1024; off <<= 1){
            int v = (tid >= off) ? sh[tid - off] : 0;
            __syncthreads();
            sh[tid] += v;
            __syncthreads();
        }
        int run = sh[tid] - own;
        for (int j = 0; j < 32; j++){
            ro[base + j] = run;
            cur[base + j] = run;
            run += cnt[base + j];
        }
        if (tid == 1023) ro[NNODES] = run;
        __syncthreads();
    }
}

__global__ void scatter_kernel(const int* __restrict__ ei, const int* __restrict__ ea){
    int e = blockIdx.x*blockDim.x + threadIdx.x;
    if (e < NEDGES){
        int d = ei[NEDGES + e];
        int s = ei[e];
        int a = ea[e];
        if (a == -2)           { int q = atomicAdd(&g_bcur[0][d], 1); g_bsrc[0][q] = s; g_bdst[0][q] = d; }
        if (a >= 0  && a <= 1) { int q = atomicAdd(&g_bcur[1][d], 1); g_bsrc[1][q] = s; g_bdst[1][q] = d; }
        if (a >= -1 && a <= 0) { int q = atomicAdd(&g_bcur[2][d], 1); g_bsrc[2][q] = s; g_bdst[2][q] = d; }
        if (a >= -1 && a <= 1) { int q = atomicAdd(&g_bcur[3][d], 1); g_bsrc[3][q] = s; g_bdst[3][q] = d; }
        if (a == -3)           { int q = atomicAdd(&g_bcur[4][d], 1); g_bsrc[4][q] = s; }
        if (a == 3)            { int q = atomicAdd(&g_bcur[5][d], 1); g_bsrc[5][q] = s; }
    }
}

// ------------------------- weight prep -------------------------
__global__ void prep_kernel(const float* __restrict__ ecA_W1, const float* __restrict__ ecA_b1,
                            const float* __restrict__ ec1_W1, const float* __restrict__ ec1_b1,
                            const float* __restrict__ ec2_W1, const float* __restrict__ ec2_b1,
                            const float* __restrict__ ec3_W1, const float* __restrict__ ec3_b1,
                            const float* __restrict__ Wl, const float* __restrict__ Wr){
    int id = blockIdx.x*blockDim.x + threadIdx.x;
    if (id < CC*256){
        int k = id >> 8, c = id & 255;
        float v;
        if (c < 128) v = ecA_W1[k*128 + c] - ecA_W1[(128+k)*128 + c];
        else         v = ecA_W1[(128+k)*128 + (c-128)];
        g_WUVA[k*256 + c] = v;
    }
    if (id < CC*768){
        int k = id / 768, c = id % 768;
        int b = c >> 8, cc = c & 255;
        const float* W1 = (b==0)? ec1_W1 : (b==1)? ec2_W1 : ec3_W1;
        float v;
        if (cc < 128) v = W1[k*128 + cc] - W1[(128+k)*128 + cc];
        else          v = W1[(128+k)*128 + (cc-128)];
        g_WUVB[k*768 + c] = v;
    }
    if (id < 256*CC){
        int k = id >> 7, c = id & 127;
        g_WCAT[id] = (k < 128) ? Wl[k*128 + c] : Wr[(k-128)*128 + c];
    }
    if (id < 256) g_BUVA[id] = (id < 128) ? ecA_b1[id] : 0.f;
    if (id < 768){
        int b = id >> 8, cc = id & 255;
        const float* bb = (b==0)? ec1_b1 : (b==1)? ec2_b1 : ec3_b1;
        g_BUVB[id] = (cc < 128) ? bb[cc] : 0.f;
    }
}

// ------------------------- TF32 helpers -------------------------
__device__ __forceinline__ uint32_t to_tf32(float x){
    uint32_t h; asm("cvt.rna.tf32.f32 %0, %1;" : "=r"(h) : "f"(x));
    return h;
}

__device__ __forceinline__ void mma8(float* c, const uint32_t* a, uint32_t b0, uint32_t b1){
    asm volatile("mma.sync.aligned.m16n8k8.row.col.f32.tf32.tf32.f32 "
        "{%0,%1,%2,%3},{%4,%5,%6,%7},{%8,%9},{%0,%1,%2,%3};"
        : "+f"(c[0]),"+f"(c[1]),"+f"(c[2]),"+f"(c[3])
        : "r"(a[0]),"r"(a[1]),"r"(a[2]),"r"(a[3]),"r"(b0),"r"(b1));
}

// W2 fragments, uint4-paired: entry(kt, ntp, lane) = {b0(nt=2ntp), b1(nt=2ntp), b0(nt=2ntp+1), b1(nt=2ntp+1)}
// where b0=W2[kt*8+tt][nt*8+gg], b1=W2[kt*8+tt+4][nt*8+gg]
__global__ void prep_frag_kernel(const float* __restrict__ W2A, const float* __restrict__ W21,
                                 const float* __restrict__ W22, const float* __restrict__ W23){
    int id = blockIdx.x*blockDim.x + threadIdx.x;
    if (id >= 4*4096) return;
    int conv = id >> 12;
    int rem = id & 4095;
    int kt = rem >> 8;
    int ntp = (rem >> 5) & 7;
    int lane = rem & 31;
    int gg = lane >> 2, tt = lane & 3;
    int nt0 = ntp*2, nt1 = ntp*2 + 1;
    const float* W2 = (conv==0)?W2A:(conv==1)?W21:(conv==2)?W22:W23;
    uint32_t* d = &g_W2F[conv][((kt*8+ntp)*32+lane)*4];
    d[0] = to_tf32(W2[(kt*8+tt  )*128 + nt0*8+gg]);
    d[1] = to_tf32(W2[(kt*8+tt+4)*128 + nt0*8+gg]);
    d[2] = to_tf32(W2[(kt*8+tt  )*128 + nt1*8+gg]);
    d[3] = to_tf32(W2[(kt*8+tt+4)*128 + nt1*8+gg]);
}

// ------------------------- TF32 tensor-core GEMM (single-pass, validated R13) -------------------------
template<bool RELU, bool ACC>
__device__ __forceinline__ void tgemm_body(const float* __restrict__ A,
                                           const float* __restrict__ B,
                                           const float* __restrict__ bias,
                                           float* __restrict__ C,
                                           int N, int K,
                                           int m0, int n0,
                                           uint32_t* As, uint32_t* Bs){
    int tid = threadIdx.x;
    int wid = tid>>5, lane = tid&31;
    int g = lane>>2, t = lane&3;
    int mtb = (wid>>2)*4;
    int ntb = (wid&3)*4;
    float acc[4][4][4];
    #pragma unroll
    for(int i=0;i<4;i++)
        #pragma unroll
        for(int j=0;j<4;j++)
            #pragma unroll
            for(int r=0;r<4;r++) acc[i][j][r]=0.f;

    for (int k0=0; k0<K; k0+=16){
        #pragma unroll
        for (int s0=0; s0<2; s0++){
            int s = tid + s0*256;
            int mt = s>>6, kt=(s>>5)&1, ln=s&31;
            int gg=ln>>2, tt=ln&3;
            const float* p  = A + (size_t)(m0+mt*16+gg)*K + (k0+kt*8+tt);
            const float* p8 = p + (size_t)8*K;
            uint32_t h0 = to_tf32(p[0]);
            uint32_t h2 = to_tf32(p[4]);
            uint32_t h1 = to_tf32(p8[0]);
            uint32_t h3 = to_tf32(p8[4]);
            uint32_t* d = As + (mt*2+kt)*128 + ln;
            d[0]=h0; d[32]=h1; d[64]=h2; d[96]=h3;
        }
        #pragma unroll
        for (int s0=0; s0<4; s0++){
            int s = tid + s0*256;
            int nt = s>>6, kt=(s>>5)&1, ln=s&31;
            int gg=ln>>2, tt=ln&3;
            const float* p = B + (size_t)(k0+kt*8+tt)*N + (n0+nt*8+gg);
            uint32_t h0 = to_tf32(p[0]);
            uint32_t h1 = to_tf32(p[(size_t)4*N]);
            uint32_t* d = Bs + (nt*2+kt)*64 + ln;
            d[0]=h0; d[32]=h1;
        }
        __syncthreads();
        #pragma unroll
        for (int kt=0; kt<2; kt++){
            uint32_t ah[4][4];
            #pragma unroll
            for (int i=0;i<4;i++){
                const uint32_t* p = As + ((mtb+i)*2+kt)*128 + lane;
                #pragma unroll
                for (int r=0;r<4;r++) ah[i][r]=p[r*32];
            }
            #pragma unroll
            for (int j=0;j<4;j++){
                const uint32_t* p = Bs + ((ntb+j)*2+kt)*64 + lane;
                uint32_t b0h=p[0], b1h=p[32];
                #pragma unroll
                for (int i=0;i<4;i++)
                    mma8(acc[i][j], ah[i], b0h, b1h);
            }
        }
        __syncthreads();
    }
    #pragma unroll
    for (int i=0;i<4;i++){
        int row = m0 + (mtb+i)*16 + g;
        #pragma unroll
        for (int j=0;j<4;j++){
            int col = n0 + (ntb+j)*8 + 2*t;
            float bz0 = bias[col], bz1 = bias[col+1];
            #pragma unroll
            for (int h=0;h<2;h++){
                float v0 = acc[i][j][h*2+0] + bz0;
                float v1 = acc[i][j][h*2+1] + bz1;
                if (RELU){ v0=fmaxf(v0,0.f); v1=fmaxf(v1,0.f); }
                float* cp = C + (size_t)(row + h*8)*N + col;
                if (ACC){ cp[0]+=v0; cp[1]+=v1; }
                else    { cp[0]=v0;  cp[1]=v1; }
            }
        }
    }
}

template<bool RELU, bool ACC>
__global__ void __launch_bounds__(256) tgemm_kernel(const float* __restrict__ A,
                                                    const float* __restrict__ B,
                                                    const float* __restrict__ bias,
                                                    float* __restrict__ C,
                                                    int N, int K){
    __shared__ uint32_t As[2048], Bs[2048];
    tgemm_body<RELU,ACC>(A,B,bias,C,N,K, blockIdx.y*128, blockIdx.x*128, As, Bs);
}

__global__ void __launch_bounds__(256) tgemm_proj_kernel(const float* __restrict__ Av,
                                                         const float* __restrict__ Aa,
                                                         const float* __restrict__ Wv,
                                                         const float* __restrict__ Wa,
                                                         const float* __restrict__ bv,
                                                         const float* __restrict__ ba,
                                                         float* __restrict__ C){
    __shared__ uint32_t As[2048], Bs[2048];
    if (blockIdx.z == 0){
        tgemm_body<false,false>(Av, Wv, bv, C, 128, 1024, blockIdx.y*128, 0, As, Bs);
    } else {
        if (blockIdx.y >= NAROWS/128) return;
        tgemm_body<false,false>(Aa, Wa, ba, C + (size_t)NVROWS*CC, 128, 1024, blockIdx.y*128, 0, As, Bs);
    }
}

__global__ void __launch_bounds__(256) tgemm_sage_kernel(const float* __restrict__ bias){
    __shared__ uint32_t As[2048], Bs[2048];
    int z = blockIdx.z;
    tgemm_body<true,false>(g_CAT[z], g_WCAT, bias, g_SOUT[z], CC, 256,
                           blockIdx.y*128, 0, As, Bs);
}

__global__ void sum_out_kernel(float* __restrict__ out){
    int i = blockIdx.x*blockDim.x + threadIdx.x;
    if (i < NOUTR*CC) out[i] = g_SOUT[0][i] + g_SOUT[1][i] + g_SOUT[2][i];
}

// ------------------------- econv via warp-level tensor-core MMA -------------------------
// Warp-private tile: ts[16][132] (pad 4 -> conflict-free). 16 edges per tile, grid-stride.
__device__ __forceinline__ void econv_mma_body(const float* __restrict__ UV, int ustride,
                                               int uoff, int voff,
                                               const uint32_t* __restrict__ W2F,
                                               const int* __restrict__ browoff,
                                               const int* __restrict__ bsrc,
                                               const int* __restrict__ bdst,
                                               unsigned* __restrict__ Hk,
                                               float* ts, int warpGlobal, int warpStride, int lane){
    int cnt = browoff[NNODES];
    int g = lane >> 2, t4 = lane & 3;
    for (int tile = warpGlobal; tile*16 < cnt; tile += warpStride){
        int base = tile*16;
        int tcnt = min(16, cnt - base);
        int eidx = base + lane;
        int sE = 0, dE = 0;
        if (lane < 16 && eidx < cnt){ sE = bsrc[eidx]; dE = bdst[eidx]; }
        // ---- gather T[e,:] = relu(u[dst]+v[src]) ----
        #pragma unroll 4
        for (int e = 0; e < 16; e++){
            float4 tv = make_float4(0.f,0.f,0.f,0.f);
            if (e < tcnt){
                int s = __shfl_sync(0xffffffffu, sE, e);
                int d = __shfl_sync(0xffffffffu, dE, e);
                float4 u = *(const float4*)(UV + (size_t)d*ustride + uoff + lane*4);
                float4 v = *(const float4*)(UV + (size_t)s*ustride + voff + lane*4);
                tv = f4relu(make_float4(u.x+v.x, u.y+v.y, u.z+v.z, u.w+v.w));
            }
            *(float4*)(ts + e*132 + lane*4) = tv;
        }
        __syncwarp();
        // ---- S = T @ W2 via mma (16x128x128) ----
        float acc[16][4];
        #pragma unroll
        for (int nt = 0; nt < 16; nt++){
            acc[nt][0]=0.f; acc[nt][1]=0.f; acc[nt][2]=0.f; acc[nt][3]=0.f;
        }
        #pragma unroll
        for (int kt = 0; kt < 16; kt++){
            uint32_t a[4];
            a[0] = to_tf32(ts[(size_t)g*132      + kt*8 + t4    ]);
            a[1] = to_tf32(ts[(size_t)(g+8)*132  + kt*8 + t4    ]);
            a[2] = to_tf32(ts[(size_t)g*132      + kt*8 + t4 + 4]);
            a[3] = to_tf32(ts[(size_t)(g+8)*132  + kt*8 + t4 + 4]);
            uint4 bq[8];
            #pragma unroll
            for (int ntp = 0; ntp < 8; ntp++)
                bq[ntp] = __ldg((const uint4*)(W2F + ((size_t)(kt*8+ntp)*32 + lane)*4));
            #pragma unroll
            for (int ntp = 0; ntp < 8; ntp++){
                mma8(acc[2*ntp+0], a, bq[ntp].x, bq[ntp].y);
                mma8(acc[2*ntp+1], a, bq[ntp].z, bq[ntp].w);
            }
        }
        __syncwarp();
        // ---- write S back into ts (C fragment: rows g,g+8; cols nt*8+2t4,+1) ----
        #pragma unroll
        for (int nt = 0; nt < 16; nt++){
            *(float2*)(ts + (size_t)g*132     + nt*8 + 2*t4) = make_float2(acc[nt][0], acc[nt][1]);
            *(float2*)(ts + (size_t)(g+8)*132 + nt*8 + 2*t4) = make_float2(acc[nt][2], acc[nt][3]);
        }
        __syncwarp();
        // ---- segmented max over dst runs ----
        int r = 0;
        while (r < tcnt){
            int d = __shfl_sync(0xffffffffu, dE, r);
            int r2 = r + 1;
            while (r2 < tcnt && __shfl_sync(0xffffffffu, dE, r2) == d) r2++;
            float4 m = *(const float4*)(ts + (size_t)r*132 + lane*4);
            for (int p = r+1; p < r2; p++)
                m = f4max(m, *(const float4*)(ts + (size_t)p*132 + lane*4));
            bool headIn = (r > 0) || (browoff[d] == base);
            bool tailIn = (r2 < tcnt) || (base + tcnt == cnt) || (browoff[d+1] == base + 16);
            unsigned* hp = Hk + (size_t)d*CC + lane*4;
            unsigned e0 = fenc(m.x), e1 = fenc(m.y), e2 = fenc(m.z), e3 = fenc(m.w);
            if (headIn && tailIn){
                hp[0]=e0; hp[1]=e1; hp[2]=e2; hp[3]=e3;
            } else {
                atomicMax(hp+0, e0); atomicMax(hp+1, e1);
                atomicMax(hp+2, e2); atomicMax(hp+3, e3);
            }
            r = r2;
        }
        __syncwarp();
    }
}

__global__ void __launch_bounds__(256) econvA_mma_kernel(){
    extern __shared__ float sts[];
    int w = threadIdx.x >> 5, lane = threadIdx.x & 31;
    econv_mma_body(g_UVA, 256, 0, 128, g_W2F[0],
                   g_browoff[0], g_bsrc[0], g_bdst[0], g_HkA,
                   sts + (size_t)w*16*132, blockIdx.x*8 + w, gridDim.x*8, lane);
}

__global__ void __launch_bounds__(256) econv3_mma_kernel(){
    extern __shared__ float sts[];
    int w = threadIdx.x >> 5, lane = threadIdx.x & 31;
    int z = blockIdx.z;
    econv_mma_body(g_UVB, 768, 256*z, 256*z + 128, g_W2F[1+z],
                   g_browoff[1+z], g_bsrc[1+z], g_bdst[1+z], (unsigned*)g_H[z],
                   sts + (size_t)w*16*132, blockIdx.x*8 + w, gridDim.x*8, lane);
}

// decode HkA -> relu(max+b2) (empty->0) -> fc dot -> ares
__global__ void finalizeA_kernel(const float* __restrict__ b2,
                                 const float* __restrict__ fcW,
                                 const float* __restrict__ fcb){
    int w = threadIdx.x >> 5, lane = threadIdx.x & 31;
    int node = blockIdx.x * 8 + w;
    if (node >= NNODES) return;
    unsigned* hp = g_HkA + (size_t)node*CC + lane*4;
    float f0 = fdec(hp[0]), f1 = fdec(hp[1]), f2 = fdec(hp[2]), f3 = fdec(hp[3]);
    float4 r;
    if (f0 < -5e29f){
        r = make_float4(0.f,0.f,0.f,0.f);
    } else {
        float4 bb = *(const float4*)(b2 + lane*4);
        r = f4relu(make_float4(f0+bb.x, f1+bb.y, f2+bb.z, f3+bb.w));
    }
    float part = r.x*fcW[lane*4] + r.y*fcW[lane*4+1] + r.z*fcW[lane*4+2] + r.w*fcW[lane*4+3];
    #pragma unroll
    for (int o = 16; o > 0; o >>= 1) part += __shfl_down_sync(0xffffffffu, part, o);
    if (lane == 0) g_ARES[node] = part + fcb[0];
}

// decode g_H[z] keys in place -> float H (empty->0, else relu(max+b2z))
__global__ void finalize3_kernel(const float* __restrict__ b2a,
                                 const float* __restrict__ b2b,
                                 const float* __restrict__ b2c){
    int w = threadIdx.x >> 5, lane = threadIdx.x & 31;
    int node = blockIdx.x * 8 + w;
    if (node >= NNODES) return;
    int z = blockIdx.z;
    const float* b2 = (z==0) ? b2a : (z==1) ? b2b : b2c;
    unsigned* hp = (unsigned*)g_H[z] + (size_t)node*CC + lane*4;
    float f0 = fdec(hp[0]), f1 = fdec(hp[1]), f2 = fdec(hp[2]), f3 = fdec(hp[3]);
    float4 r;
    if (f0 < -5e29f){
        r = make_float4(0.f,0.f,0.f,0.f);
    } else {
        float4 bb = *(const float4*)(b2 + lane*4);
        r = f4relu(make_float4(f0+bb.x, f1+bb.y, f2+bb.z, f3+bb.w));
    }
    float* fp = (float*)hp;
    fp[0]=r.x; fp[1]=r.y; fp[2]=r.z; fp[3]=r.w;
}

// ------------------------- per-node graph kernels (masked lists) -------------------------
__global__ void vpa_kernel(){
    int w = threadIdx.x >> 5, lane = threadIdx.x & 31;
    int node = blockIdx.x * 8 + w;
    if (node >= NNODES) return;
    const float4* X4 = (const float4*)g_X;
    float4 xd = X4[(size_t)node*32 + lane];
    int p = g_browoff[4][node], pe = g_browoff[4][node+1];
    float4 o;
    if (p < pe){
        float4 m = make_float4(-1e30f,-1e30f,-1e30f,-1e30f);
        for (; p < pe; p++){
            float4 xs = X4[(size_t)g_bsrc[4][p]*32 + lane];
            m = f4max(m, make_float4(xd.x+xs.x, xd.y+xs.y, xd.z+xs.z, xd.w+xs.w));
        }
        o = f4relu(m);
    } else {
        o = make_float4(0.f,0.f,0.f,0.f);
    }
    ((float4*)g_XAG)[(size_t)node*32 + lane] = o;
}

__global__ void acv_kernel(){
    int w = threadIdx.x >> 5, lane = threadIdx.x & 31;
    int node = blockIdx.x * 8 + w;
    if (node >= NNODES) return;
    const float4* X4 = (const float4*)g_X;
    float4 xd = X4[(size_t)node*32 + lane];
    float4 acc = make_float4(0.f,0.f,0.f,0.f);
    int p = g_browoff[5][node], pe = g_browoff[5][node+1];
    for (; p < pe; p++){
        int s = g_bsrc[5][p];
        float wgt = g_ARES[s];
        float4 xs = X4[(size_t)s*32 + lane];
        acc.x += wgt*xs.x + xd.x;
        acc.y += wgt*xs.y + xd.y;
        acc.z += wgt*xs.z + xd.z;
        acc.w += wgt*xs.w + xd.w;
    }
    ((float4*)g_XV2)[(size_t)node*32 + lane] = f4relu(acc);
}

__global__ void cat3_kernel(const int* __restrict__ spkp){
    int w = threadIdx.x >> 5, lane = threadIdx.x & 31;
    int r = blockIdx.x * 8 + w;
    if (r >= NOUTR) return;
    int z = blockIdx.z;
    int spk = spkp ? spkp[0] : 3;
    int node = (r >> 7) * spk * 128 + (r & 127);
    const float4* H4 = (const float4*)g_H[z];
    const int* browoff = g_browoff[1+z];
    const int* bsrc = g_bsrc[1+z];
    float4 s = make_float4(0.f,0.f,0.f,0.f);
    int p = browoff[node], pe = browoff[node+1];
    int cnt = pe - p;
    for (; p < pe; p++){
        float4 hs = H4[(size_t)bsrc[p]*32 + lane];
        s.x += hs.x; s.y += hs.y; s.z += hs.z; s.w += hs.w;
    }
    float inv = cnt ? 1.f/(float)cnt : 0.f;
    float4* C4 = (float4*)g_CAT[z];
    C4[(size_t)r*64 + lane]      = make_float4(s.x*inv, s.y*inv, s.z*inv, s.w*inv);
    C4[(size_t)r*64 + 32 + lane] = H4[(size_t)node*32 + lane];
}

// ------------------------- launch -------------------------
extern "C" void kernel_launch(void* const* d_in, const int* in_sizes, int n_in,
                              void* d_out, int out_size){
    const float* x_visual = (const float*)d_in[0];
    const float* x_audio  = (const float*)d_in[1];
    const float* W011 = (const float*)d_in[2];
    const float* b011 = (const float*)d_in[3];
    const float* W012 = (const float*)d_in[4];
    const float* b012 = (const float*)d_in[5];
    const float* ecA_W1 = (const float*)d_in[6];
    const float* ecA_b1 = (const float*)d_in[7];
    const float* ecA_W2 = (const float*)d_in[8];
    const float* ecA_b2 = (const float*)d_in[9];
    const float* ec1_W1 = (const float*)d_in[10];
    const float* ec1_b1 = (const float*)d_in[11];
    const float* ec1_W2 = (const float*)d_in[12];
    const float* ec1_b2 = (const float*)d_in[13];
    const float* ec2_W1 = (const float*)d_in[14];
    const float* ec2_b1 = (const float*)d_in[15];
    const float* ec2_W2 = (const float*)d_in[16];
    const float* ec2_b2 = (const float*)d_in[17];
    const float* ec3_W1 = (const float*)d_in[18];
    const float* ec3_b1 = (const float*)d_in[19];
    const float* ec3_W2 = (const float*)d_in[20];
    const float* ec3_b2 = (const float*)d_in[21];
    const float* sage_Wl = (const float*)d_in[22];
    const float* sage_bl = (const float*)d_in[23];
    const float* sage_Wr = (const float*)d_in[24];
    const float* fc_W = (const float*)d_in[25];
    const float* fc_b = (const float*)d_in[26];
    const int* edge_index = (const int*)d_in[27];
    const int* edge_attr  = (const int*)d_in[28];
    const int* speakers   = (n_in > 29) ? (const int*)d_in[29] : nullptr;
    float* out = (float*)d_out;

    float *pX, *pXAG, *pXV2, *pUVA, *pUVB;
    float *pWUVA, *pBUVA, *pWUVB, *pBUVB;
    cudaGetSymbolAddress((void**)&pX,    g_X);
    cudaGetSymbolAddress((void**)&pXAG,  g_XAG);
    cudaGetSymbolAddress((void**)&pXV2,  g_XV2);
    cudaGetSymbolAddress((void**)&pUVA,  g_UVA);
    cudaGetSymbolAddress((void**)&pUVB,  g_UVB);
    cudaGetSymbolAddress((void**)&pWUVA, g_WUVA);
    cudaGetSymbolAddress((void**)&pBUVA, g_BUVA);
    cudaGetSymbolAddress((void**)&pWUVB, g_WUVB);
    cudaGetSymbolAddress((void**)&pBUVB, g_BUVB);

    static cudaStream_t s2 = nullptr;
    static cudaEvent_t evF = nullptr, evJ = nullptr;
    static bool init_done = false;
    if (!init_done){
        cudaFuncSetAttribute(econvA_mma_kernel, cudaFuncAttributeMaxDynamicSharedMemorySize, 8*16*132*4);
        cudaFuncSetAttribute(econv3_mma_kernel, cudaFuncAttributeMaxDynamicSharedMemorySize, 8*16*132*4);
        cudaStreamCreateWithFlags(&s2, cudaStreamNonBlocking);
        cudaEventCreateWithFlags(&evF, cudaEventDisableTiming);
        cudaEventCreateWithFlags(&evJ, cudaEventDisableTiming);
        init_done = true;
    }
    const int ECONV_SMEM = 8*16*132*4;  // 67584 B

    // ---- fork: side stream runs CSR build + prep + frag + H-init, main runs proj ----
    cudaEventRecord(evF, 0);
    cudaStreamWaitEvent(s2, evF, 0);

    initzero_kernel<<<(3*NNODES*CC)/256, 256, 0, s2>>>();
    hist_kernel<<<NEDGES/256, 256, 0, s2>>>(edge_index, edge_attr);
    scan_kernel<<<1, 1024, 0, s2>>>();
    scatter_kernel<<<NEDGES/256, 256, 0, s2>>>(edge_index, edge_attr);
    prep_kernel<<<(CC*768 + 255)/256, 256, 0, s2>>>(ecA_W1, ecA_b1, ec1_W1, ec1_b1,
                                                    ec2_W1, ec2_b1, ec3_W1, ec3_b1,
                                                    sage_Wl, sage_Wr);
    prep_frag_kernel<<<(4*4096)/256, 256, 0, s2>>>(ecA_W2, ec1_W2, ec2_W2, ec3_W2);
    cudaEventRecord(evJ, s2);

    // main stream: input projections -> X (independent of side chain)
    tgemm_proj_kernel<<<dim3(1, NVROWS/128, 2), 256>>>(x_visual, x_audio, W011, W012, b011, b012, pX);

    // join
    cudaStreamWaitEvent(0, evJ, 0);

    // xa_g
    vpa_kernel<<<NNODES/8, 256>>>();

    // u,v for ecA
    tgemm_kernel<false,false><<<dim3(2, NNODES/128), 256>>>(pXAG, pWUVA, pBUVA, pUVA, 256, CC);

    // ecA edge conv (tensor-core) -> finalize (fc fused) -> ares
    econvA_mma_kernel<<<512, 256, ECONV_SMEM>>>();
    finalizeA_kernel<<<NNODES/8, 256>>>(ecA_b2, fc_W, fc_b);

    // xv2
    acv_kernel<<<NNODES/8, 256>>>();

    // u,v for the 3 branches
    tgemm_kernel<false,false><<<dim3(6, NNODES/128), 256>>>(pXV2, pWUVB, pBUVB, pUVB, 768, CC);

    // 3 branch econvs (tensor-core) + finalize
    econv3_mma_kernel<<<dim3(512, 1, 3), 256, ECONV_SMEM>>>();
    finalize3_kernel<<<dim3(NNODES/8, 1, 3), 256>>>(ec1_b2, ec2_b2, ec3_b2);

    // cat for all 3 branches
    cat3_kernel<<<dim3(NOUTR/8, 1, 3), 256>>>(speakers);

    // SAGE gemm + sum
    tgemm_sage_kernel<<<dim3(1, NOUTR/128, 3), 256>>>(sage_bl);
    sum_out_kernel<<<(NOUTR*CC)/256, 256>>>(out);
}